// round 8
// baseline (speedup 1.0000x reference)
#include <cuda_runtime.h>
#include <math.h>
#include <stdint.h>

// ---------------- problem constants ----------------
#define NB 2
#define NT 2048
#define NC 2048
#define NH 16
#define ND 128
#define C3 (3 * NC)      /* 6144 */
#define BT (NB * NT)     /* 4096 */

#define RMS_EPS 1.1920929e-07f
#define SM_SCALE (1.0f / 128.0f)

// ---------------- scratch (device globals; no allocs allowed) ----------------
__device__ float g_qkv[(size_t)BT * C3];      // ~100.7 MB
__device__ float g_y[(size_t)BT * NC];        // ~33.6 MB
__device__ float g_xt[(size_t)BT * NC];       // ~33.6 MB
__device__ float g_wqkvT[(size_t)C3 * NC];    // ~50.3 MB
__device__ float g_wprojT[(size_t)NC * NC];   // ~16.8 MB
__device__ float g_cos[NT * 64];
__device__ float g_sin[NT * 64];

// ---------------- helpers ----------------
__device__ __forceinline__ float tf32r(float x) {
    uint32_t o;
    asm("cvt.rna.tf32.f32 %0, %1;" : "=r"(o) : "f"(x));
    return __uint_as_float(o);
}

__device__ __forceinline__ void mma_tf32(float c[4],
                                         uint32_t a0, uint32_t a1, uint32_t a2, uint32_t a3,
                                         uint32_t b0, uint32_t b1) {
    asm volatile(
        "mma.sync.aligned.m16n8k8.row.col.f32.tf32.tf32.f32 "
        "{%0,%1,%2,%3}, {%4,%5,%6,%7}, {%8,%9}, {%0,%1,%2,%3};"
        : "+f"(c[0]), "+f"(c[1]), "+f"(c[2]), "+f"(c[3])
        : "r"(a0), "r"(a1), "r"(a2), "r"(a3), "r"(b0), "r"(b1));
}

__device__ __forceinline__ uint32_t smem_u32(const void* p) {
    uint32_t a;
    asm("{ .reg .u64 t; cvta.to.shared.u64 t, %1; cvt.u32.u64 %0, t; }"
        : "=r"(a) : "l"(p));
    return a;
}

__device__ __forceinline__ void cp_async16(uint32_t dst, const void* src) {
    asm volatile("cp.async.cg.shared.global [%0], [%1], 16;" :: "r"(dst), "l"(src));
}
#define CP_COMMIT() asm volatile("cp.async.commit_group;" ::: "memory")
#define CP_WAIT0()  asm volatile("cp.async.wait_group 0;" ::: "memory")
#define CP_WAIT1()  asm volatile("cp.async.wait_group 1;" ::: "memory")

// ============================================================
// RoPE tables
// ============================================================
__global__ void rope_tables_kernel() {
    int idx = blockIdx.x * blockDim.x + threadIdx.x;
    if (idx >= NT * 64) return;
    int t = idx >> 6;
    int i = idx & 63;
    double inv_f = exp(-((double)i / 64.0) * log(1.0e6));
    double ang = (double)t * inv_f;
    g_cos[idx] = (float)cos(ang);
    g_sin[idx] = (float)sin(ang);
}

// ============================================================
// tf32-round copy
// ============================================================
__global__ __launch_bounds__(256) void cvt_copy_kernel(
    const float4* __restrict__ in, float4* __restrict__ out, int n4)
{
    int i = blockIdx.x * blockDim.x + threadIdx.x;
    if (i >= n4) return;
    float4 v = in[i];
    v.x = tf32r(v.x); v.y = tf32r(v.y); v.z = tf32r(v.z); v.w = tf32r(v.w);
    out[i] = v;
}

// ============================================================
// Transpose + tf32 round
// ============================================================
__global__ __launch_bounds__(256) void transpose_kernel(
    const float* __restrict__ in, float* __restrict__ out, int R, int Ccols)
{
    __shared__ float tile[32][33];
    int c0 = blockIdx.x * 32, r0 = blockIdx.y * 32;
    int tx = threadIdx.x, ty = threadIdx.y;
#pragma unroll
    for (int j = 0; j < 32; j += 8)
        tile[ty + j][tx] = in[(size_t)(r0 + ty + j) * Ccols + c0 + tx];
    __syncthreads();
#pragma unroll
    for (int j = 0; j < 32; j += 8)
        out[(size_t)(c0 + ty + j) * R + r0 + tx] = tf32r(tile[tx][ty + j]);
}

// ============================================================
// tf32 mma.sync GEMM v3: C[M,N] = A[M,K] @ Bt[N,K]^T
// Block tile 128x256, BK=32, 512 threads = 16 warps (4m x 4n),
// warp tile 32x64. 3-stage cp.async ring, ONE barrier per chunk.
// ============================================================
#define G3_BM 128
#define G3_BN 256
#define G3_STG_FLOATS 13824                 /* A 128*36 + B 256*36 */
#define G3_STG_BYTES  55296
#define G3_SMEM_BYTES (3 * G3_STG_BYTES)    /* 165888 */

__global__ __launch_bounds__(512, 1) void gemm_mma3_kernel(
    const float* __restrict__ A, const float* __restrict__ Bt,
    float* __restrict__ Cm, int M, int N, int K)
{
    extern __shared__ float sm[];
    const uint32_t smb = smem_u32(sm);

    const int tid = threadIdx.x;
    const int wid = tid >> 5;
    const int lane = tid & 31;
    const int gid = lane >> 2;
    const int tig = lane & 3;
    const int wm = wid & 3;          // 4 m-warps, 32 rows each
    const int wn = wid >> 2;         // 4 n-warps, 64 cols each
    const int m0 = blockIdx.y << 7;
    const int n0 = blockIdx.x << 8;

    const int ar = tid >> 3;         // 0..63
    const int ak = (tid & 7) << 2;   // 0,4,...,28

    float acc[2][8][4];
#pragma unroll
    for (int i = 0; i < 2; i++)
#pragma unroll
        for (int j = 0; j < 8; j++)
#pragma unroll
            for (int e = 0; e < 4; e++) acc[i][j][e] = 0.0f;

    const int nt = K >> 5;           // 64

    // A rows: ar + 64i (i<2); B rows: ar + 64i (i<4). dst stride 36 floats.
#define G3_ISSUE(t_)                                                          \
    do {                                                                      \
        const int _k0 = (t_) << 5;                                            \
        const uint32_t _sb = smb + ((t_) % 3) * G3_STG_BYTES;                 \
        _Pragma("unroll")                                                     \
        for (int _i = 0; _i < 2; _i++) {                                      \
            int _r = ar + (_i << 6);                                          \
            cp_async16(_sb + (_r * 36 + ak) * 4,                              \
                       A + (size_t)(m0 + _r) * K + _k0 + ak);                 \
        }                                                                     \
        _Pragma("unroll")                                                     \
        for (int _i = 0; _i < 4; _i++) {                                      \
            int _r = ar + (_i << 6);                                          \
            cp_async16(_sb + 18432 + (_r * 36 + ak) * 4,                      \
                       Bt + (size_t)(n0 + _r) * K + _k0 + ak);                \
        }                                                                     \
    } while (0)

    G3_ISSUE(0); CP_COMMIT();
    G3_ISSUE(1); CP_COMMIT();

    const int mbase = wm << 5;
    const int nbase = wn << 6;

    for (int t = 0; t < nt; t++) {
        CP_WAIT1();
        __syncthreads();
        // Single barrier per chunk: readers of stage (t-1)%3 (the one this
        // issue overwrites) all passed this barrier after their iter t-1
        // compute, so the overwrite is safe.
        if (t + 2 < nt) G3_ISSUE(t + 2);
        CP_COMMIT();

        const uint32_t* Au = (const uint32_t*)(sm + (t % 3) * G3_STG_FLOATS);
        const uint32_t* Bu = Au + 4608;
#pragma unroll
        for (int ks = 0; ks < 4; ks++) {
            const int kb = ks << 3;
            uint32_t af[2][4];
#pragma unroll
            for (int mf = 0; mf < 2; mf++) {
                int r0_ = (mbase + (mf << 4) + gid) * 36 + kb + tig;
                af[mf][0] = Au[r0_];
                af[mf][1] = Au[r0_ + 8 * 36];
                af[mf][2] = Au[r0_ + 4];
                af[mf][3] = Au[r0_ + 8 * 36 + 4];
            }
            uint32_t bf[8][2];
#pragma unroll
            for (int nf = 0; nf < 8; nf++) {
                int nr = (nbase + (nf << 3) + gid) * 36 + kb + tig;
                bf[nf][0] = Bu[nr];
                bf[nf][1] = Bu[nr + 4];
            }
#pragma unroll
            for (int mf = 0; mf < 2; mf++)
#pragma unroll
                for (int nf = 0; nf < 8; nf++)
                    mma_tf32(acc[mf][nf], af[mf][0], af[mf][1], af[mf][2], af[mf][3],
                             bf[nf][0], bf[nf][1]);
        }
    }
#undef G3_ISSUE

    // epilogue
#pragma unroll
    for (int mf = 0; mf < 2; mf++) {
#pragma unroll
        for (int nf = 0; nf < 8; nf++) {
            int r0_ = m0 + mbase + (mf << 4) + gid;
            int c = n0 + nbase + (nf << 3) + (tig << 1);
            *(float2*)&Cm[(size_t)r0_ * N + c] = make_float2(acc[mf][nf][0], acc[mf][nf][1]);
            *(float2*)&Cm[(size_t)(r0_ + 8) * N + c] = make_float2(acc[mf][nf][2], acc[mf][nf][3]);
        }
    }
}

// ============================================================
// RMSNorm + RoPE in-place on q,k; tf32-round q,k,v.
// ============================================================
__global__ __launch_bounds__(256) void rmsrope_kernel(
    const float* __restrict__ qw, const float* __restrict__ kw)
{
    const int tok = blockIdx.x;
    const int t = tok & (NT - 1);
    const int warp = threadIdx.x >> 5;
    const int lane = threadIdx.x & 31;

    const float c0 = g_cos[t * 64 + lane];
    const float s0 = g_sin[t * 64 + lane];
    const float c1 = g_cos[t * 64 + 32 + lane];
    const float s1 = g_sin[t * 64 + 32 + lane];

#pragma unroll
    for (int s = 0; s < 4; s++) {
        int task = warp + (s << 3);
        int isK = task >> 4;
        int h = task & 15;
        const float* w = isK ? kw : qw;
        size_t rbase = (size_t)tok * C3 + (size_t)isK * 2048 + (size_t)h * ND;

        float x0 = g_qkv[rbase + lane];
        float x1 = g_qkv[rbase + lane + 32];
        float x2 = g_qkv[rbase + lane + 64];
        float x3 = g_qkv[rbase + lane + 96];

        float ss = x0 * x0 + x1 * x1 + x2 * x2 + x3 * x3;
#pragma unroll
        for (int off = 16; off > 0; off >>= 1)
            ss += __shfl_xor_sync(0xffffffffu, ss, off);
        float inv = 1.0f / sqrtf(ss * (1.0f / (float)ND) + RMS_EPS);

        float n0 = x0 * inv * w[lane];
        float n1 = x1 * inv * w[lane + 32];
        float n2 = x2 * inv * w[lane + 64];
        float n3 = x3 * inv * w[lane + 96];

        g_qkv[rbase + lane]       = tf32r(n0 * c0 - n2 * s0);
        g_qkv[rbase + lane + 32]  = tf32r(n1 * c1 - n3 * s1);
        g_qkv[rbase + lane + 64]  = tf32r(n2 * c0 + n0 * s0);
        g_qkv[rbase + lane + 96]  = tf32r(n3 * c1 + n1 * s1);
    }

    {
        float4* vsec = (float4*)&g_qkv[(size_t)tok * C3 + 4096];
#pragma unroll
        for (int i = 0; i < 2; i++) {
            int idx = threadIdx.x + (i << 8);
            float4 v = vsec[idx];
            v.x = tf32r(v.x); v.y = tf32r(v.y); v.z = tf32r(v.z); v.w = tf32r(v.w);
            vsec[idx] = v;
        }
    }
}

// ============================================================
// Flash attention with tf32 mma.sync (unchanged from R4/R5)
// ============================================================
#define FK_QS   0
#define FK_STG  17152
#define FK_KS(s) (8448 + (s) * FK_STG)
#define FK_VS(s) (8448 + (s) * FK_STG + 8448)
#define FK_PS   42752
#define FK_RM   47104
#define FK_RS   47232
#define FK_FLOATS 47360
#define FK_SMEM_BYTES (FK_FLOATS * 4)

__global__ __launch_bounds__(256, 1) void flash_mma_kernel()
{
    extern __shared__ float sm[];
    const uint32_t smb = smem_u32(sm);

    const int tid = threadIdx.x;
    const int lane = tid & 31;
    const int wid = tid >> 5;
    const int gid = lane >> 2;
    const int tig = lane & 3;
    const int wm = wid & 3;
    const int wn = wid >> 2;
    const int mbase = wm << 4;

    const int qb = blockIdx.x;
    const int bh = blockIdx.y;
    const int b = bh >> 4;
    const int h = bh & 15;
    const int q0 = qb << 6;

    const size_t base = (size_t)b * NT * C3 + (size_t)h * ND;

#pragma unroll
    for (int i = 0; i < 8; i++) {
        int f = tid + (i << 8);
        int r = f >> 5;
        int d4 = (f & 31) << 2;
        float4 v = *(const float4*)&g_qkv[base + (size_t)(q0 + r) * C3 + d4];
        *(float4*)&sm[FK_QS + r * 132 + d4] = v;
    }

    {
        const int k0 = 0, bufi = 0;
#pragma unroll
        for (int i = 0; i < 8; i++) {
            int f = tid + (i << 8);
            int r = f >> 5;
            int d4 = (f & 31) << 2;
            const float* srcK = &g_qkv[base + (size_t)(k0 + r) * C3 + 2048 + d4];
            const float* srcV = &g_qkv[base + (size_t)(k0 + r) * C3 + 4096 + d4];
            cp_async16(smb + (FK_KS(bufi) + r * 132 + d4) * 4, srcK);
            cp_async16(smb + (FK_VS(bufi) + r * 136 + d4) * 4, srcV);
        }
        CP_COMMIT();
    }

    float o[8][4];
#pragma unroll
    for (int j = 0; j < 8; j++)
#pragma unroll
        for (int e = 0; e < 4; e++) o[j][e] = 0.0f;
    float m0_ = -INFINITY, m1_ = -INFINITY, l0_ = 0.0f, l1_ = 0.0f;

    const uint32_t* Qu = (const uint32_t*)(sm + FK_QS);
    uint32_t* Pu = (uint32_t*)(sm + FK_PS);
    float* Pf = sm + FK_PS;
    float* redm = sm + FK_RM;
    float* reds = sm + FK_RS;

    for (int kt = 0; kt <= qb; kt++) {
        CP_WAIT0();
        __syncthreads();
        if (kt < qb) {
            const int k0n = (kt + 1) << 6;
            const int bufn = (kt + 1) & 1;
#pragma unroll
            for (int i = 0; i < 8; i++) {
                int f = tid + (i << 8);
                int r = f >> 5;
                int d4 = (f & 31) << 2;
                const float* srcK = &g_qkv[base + (size_t)(k0n + r) * C3 + 2048 + d4];
                const float* srcV = &g_qkv[base + (size_t)(k0n + r) * C3 + 4096 + d4];
                cp_async16(smb + (FK_KS(bufn) + r * 132 + d4) * 4, srcK);
                cp_async16(smb + (FK_VS(bufn) + r * 136 + d4) * 4, srcV);
            }
            CP_COMMIT();
        }

        const int bufi = kt & 1;
        const uint32_t* Ku = (const uint32_t*)(sm + FK_KS(bufi));
        const uint32_t* Vu = (const uint32_t*)(sm + FK_VS(bufi));
        const int k0 = kt << 6;

        float s[4][4];
#pragma unroll
        for (int j = 0; j < 4; j++)
#pragma unroll
            for (int e = 0; e < 4; e++) s[j][e] = 0.0f;

#pragma unroll
        for (int kb = 0; kb < 128; kb += 8) {
            int ai = (mbase + gid) * 132 + kb + tig;
            uint32_t a0 = Qu[ai];
            uint32_t a1 = Qu[ai + 8 * 132];
            uint32_t a2 = Qu[ai + 4];
            uint32_t a3 = Qu[ai + 8 * 132 + 4];
#pragma unroll
            for (int j = 0; j < 4; j++) {
                int nr = ((wn << 5) + (j << 3) + gid) * 132 + kb + tig;
                uint32_t b0 = Ku[nr];
                uint32_t b1 = Ku[nr + 4];
                mma_tf32(s[j], a0, a1, a2, a3, b0, b1);
            }
        }

        const int r0g = q0 + mbase + gid;
        const int r1g = r0g + 8;
        if (kt == qb) {
#pragma unroll
            for (int j = 0; j < 4; j++) {
                int cbase = k0 + (wn << 5) + (j << 3) + (tig << 1);
                s[j][0] = (cbase     <= r0g) ? s[j][0] * SM_SCALE : -1e30f;
                s[j][1] = (cbase + 1 <= r0g) ? s[j][1] * SM_SCALE : -1e30f;
                s[j][2] = (cbase     <= r1g) ? s[j][2] * SM_SCALE : -1e30f;
                s[j][3] = (cbase + 1 <= r1g) ? s[j][3] * SM_SCALE : -1e30f;
            }
        } else {
#pragma unroll
            for (int j = 0; j < 4; j++) {
                s[j][0] *= SM_SCALE; s[j][1] *= SM_SCALE;
                s[j][2] *= SM_SCALE; s[j][3] *= SM_SCALE;
            }
        }

        float pm0 = fmaxf(fmaxf(s[0][0], s[0][1]), fmaxf(s[1][0], s[1][1]));
        pm0 = fmaxf(pm0, fmaxf(fmaxf(s[2][0], s[2][1]), fmaxf(s[3][0], s[3][1])));
        float pm1 = fmaxf(fmaxf(s[0][2], s[0][3]), fmaxf(s[1][2], s[1][3]));
        pm1 = fmaxf(pm1, fmaxf(fmaxf(s[2][2], s[2][3]), fmaxf(s[3][2], s[3][3])));
        pm0 = fmaxf(pm0, __shfl_xor_sync(0xffffffffu, pm0, 1));
        pm0 = fmaxf(pm0, __shfl_xor_sync(0xffffffffu, pm0, 2));
        pm1 = fmaxf(pm1, __shfl_xor_sync(0xffffffffu, pm1, 1));
        pm1 = fmaxf(pm1, __shfl_xor_sync(0xffffffffu, pm1, 2));
        if (tig == 0) {
            redm[(wn << 6) + mbase + gid] = pm0;
            redm[(wn << 6) + mbase + gid + 8] = pm1;
        }
        __syncthreads();
        float mn0 = fmaxf(m0_, fmaxf(pm0, redm[((wn ^ 1) << 6) + mbase + gid]));
        float mn1 = fmaxf(m1_, fmaxf(pm1, redm[((wn ^ 1) << 6) + mbase + gid + 8]));
        float corr0 = __expf(m0_ - mn0);
        float corr1 = __expf(m1_ - mn1);

        float ps0 = 0.0f, ps1 = 0.0f;
#pragma unroll
        for (int j = 0; j < 4; j++) {
            float p00 = __expf(s[j][0] - mn0);
            float p01 = __expf(s[j][1] - mn0);
            float p10 = __expf(s[j][2] - mn1);
            float p11 = __expf(s[j][3] - mn1);
            ps0 += p00 + p01;
            ps1 += p10 + p11;
            int c = (wn << 5) + (j << 3) + (tig << 1);
            *(float2*)&Pf[(mbase + gid) * 68 + c] = make_float2(tf32r(p00), tf32r(p01));
            *(float2*)&Pf[(mbase + gid + 8) * 68 + c] = make_float2(tf32r(p10), tf32r(p11));
        }
        ps0 += __shfl_xor_sync(0xffffffffu, ps0, 1);
        ps0 += __shfl_xor_sync(0xffffffffu, ps0, 2);
        ps1 += __shfl_xor_sync(0xffffffffu, ps1, 1);
        ps1 += __shfl_xor_sync(0xffffffffu, ps1, 2);
        if (tig == 0) {
            reds[(wn << 6) + mbase + gid] = ps0;
            reds[(wn << 6) + mbase + gid + 8] = ps1;
        }
        __syncthreads();
        l0_ = l0_ * corr0 + ps0 + reds[((wn ^ 1) << 6) + mbase + gid];
        l1_ = l1_ * corr1 + ps1 + reds[((wn ^ 1) << 6) + mbase + gid + 8];
        m0_ = mn0; m1_ = mn1;
#pragma unroll
        for (int j = 0; j < 8; j++) {
            o[j][0] *= corr0; o[j][1] *= corr0;
            o[j][2] *= corr1; o[j][3] *= corr1;
        }

#pragma unroll
        for (int kb = 0; kb < 64; kb += 8) {
            int ai = (mbase + gid) * 68 + kb + tig;
            uint32_t a0 = Pu[ai];
            uint32_t a1 = Pu[ai + 8 * 68];
            uint32_t a2 = Pu[ai + 4];
            uint32_t a3 = Pu[ai + 8 * 68 + 4];
#pragma unroll
            for (int j = 0; j < 8; j++) {
                int dcol = (wn << 6) + (j << 3) + gid;
                uint32_t b0 = Vu[(kb + tig) * 136 + dcol];
                uint32_t b1 = Vu[(kb + tig + 4) * 136 + dcol];
                mma_tf32(o[j], a0, a1, a2, a3, b0, b1);
            }
        }
    }

    const float inv0 = 1.0f / l0_;
    const float inv1 = 1.0f / l1_;
    const int r0g = q0 + mbase + gid;
    const size_t y0 = ((size_t)b * NT + r0g) * NC + (size_t)h * ND;
    const size_t y1 = y0 + (size_t)8 * NC;
#pragma unroll
    for (int j = 0; j < 8; j++) {
        int c = (wn << 6) + (j << 3) + (tig << 1);
        *(float2*)&g_y[y0 + c] = make_float2(tf32r(o[j][0] * inv0), tf32r(o[j][1] * inv0));
        *(float2*)&g_y[y1 + c] = make_float2(tf32r(o[j][2] * inv1), tf32r(o[j][3] * inv1));
    }
}

// ============================================================
// launch
// ============================================================
extern "C" void kernel_launch(void* const* d_in, const int* in_sizes, int n_in,
                              void* d_out, int out_size)
{
    const float* x      = (const float*)d_in[0];
    const float* w_qkv  = (const float*)d_in[1];
    const float* w_proj = (const float*)d_in[2];
    const float* qw     = (const float*)d_in[3];
    const float* kw     = (const float*)d_in[4];
    float* out = (float*)d_out;

    float* qkv_ptr = nullptr;
    float* y_ptr = nullptr;
    float* xt_ptr = nullptr;
    float* wqkvT_ptr = nullptr;
    float* wprojT_ptr = nullptr;
    cudaGetSymbolAddress((void**)&qkv_ptr, g_qkv);
    cudaGetSymbolAddress((void**)&y_ptr, g_y);
    cudaGetSymbolAddress((void**)&xt_ptr, g_xt);
    cudaGetSymbolAddress((void**)&wqkvT_ptr, g_wqkvT);
    cudaGetSymbolAddress((void**)&wprojT_ptr, g_wprojT);

    cudaFuncSetAttribute(gemm_mma3_kernel,
                         cudaFuncAttributeMaxDynamicSharedMemorySize, G3_SMEM_BYTES);
    cudaFuncSetAttribute(flash_mma_kernel,
                         cudaFuncAttributeMaxDynamicSharedMemorySize, FK_SMEM_BYTES);

    // 1. RoPE tables
    rope_tables_kernel<<<(NT * 64 + 255) / 256, 256>>>();

    // 2. tf32-rounded operands
    {
        int n4 = BT * NC / 4;
        cvt_copy_kernel<<<(n4 + 255) / 256, 256>>>((const float4*)x, (float4*)xt_ptr, n4);
        dim3 blk(32, 8);
        transpose_kernel<<<dim3(C3 / 32, NC / 32), blk>>>(w_qkv, wqkvT_ptr, NC, C3);
        transpose_kernel<<<dim3(NC / 32, NC / 32), blk>>>(w_proj, wprojT_ptr, NC, NC);
    }

    // 3. qkv = x @ w_qkv
    {
        dim3 grid(C3 / G3_BN, BT / G3_BM);
        gemm_mma3_kernel<<<grid, 512, G3_SMEM_BYTES>>>(xt_ptr, wqkvT_ptr, qkv_ptr, BT, C3, NC);
    }

    // 4. RMSNorm + RoPE
    rmsrope_kernel<<<BT, 256>>>(qw, kw);

    // 5. flash attention
    {
        dim3 grid(NT / 64, NB * NH);
        flash_mma_kernel<<<grid, 256, FK_SMEM_BYTES>>>();
    }

    // 6. out = y @ w_proj
    {
        dim3 grid(NC / G3_BN, BT / G3_BM);
        gemm_mma3_kernel<<<grid, 512, G3_SMEM_BYTES>>>(y_ptr, wprojT_ptr, out, BT, NC, NC);
    }
}

// round 9
// speedup vs baseline: 1.0506x; 1.0506x over previous
#include <cuda_runtime.h>
#include <math.h>
#include <stdint.h>

// ---------------- problem constants ----------------
#define NB 2
#define NT 2048
#define NC 2048
#define NH 16
#define ND 128
#define C3 (3 * NC)      /* 6144 */
#define BT (NB * NT)     /* 4096 */

#define RMS_EPS 1.1920929e-07f
#define SM_SCALE (1.0f / 128.0f)

// ---------------- scratch ----------------
__device__ float g_qkv[(size_t)BT * C3];
__device__ float g_y[(size_t)BT * NC];
__device__ float g_xt[(size_t)BT * NC];
__device__ float g_wqkvT[(size_t)C3 * NC];
__device__ float g_wprojT[(size_t)NC * NC];
__device__ float g_cos[NT * 64];
__device__ float g_sin[NT * 64];

// ---------------- helpers ----------------
__device__ __forceinline__ float tf32r(float x) {
    uint32_t o;
    asm("cvt.rna.tf32.f32 %0, %1;" : "=r"(o) : "f"(x));
    return __uint_as_float(o);
}

__device__ __forceinline__ void mma_tf32(float c[4],
                                         uint32_t a0, uint32_t a1, uint32_t a2, uint32_t a3,
                                         uint32_t b0, uint32_t b1) {
    asm volatile(
        "mma.sync.aligned.m16n8k8.row.col.f32.tf32.tf32.f32 "
        "{%0,%1,%2,%3}, {%4,%5,%6,%7}, {%8,%9}, {%0,%1,%2,%3};"
        : "+f"(c[0]), "+f"(c[1]), "+f"(c[2]), "+f"(c[3])
        : "r"(a0), "r"(a1), "r"(a2), "r"(a3), "r"(b0), "r"(b1));
}

// ldmatrix x4: loads 4 8x8-b16 quadrants; for b32 tiles we use
// quadrant = (row-group, 16B half). Caller supplies per-lane address.
__device__ __forceinline__ void ldsm_x4(uint32_t& r0, uint32_t& r1,
                                        uint32_t& r2, uint32_t& r3, uint32_t addr) {
    asm volatile("ldmatrix.sync.aligned.m8n8.x4.shared.b16 {%0,%1,%2,%3}, [%4];"
        : "=r"(r0), "=r"(r1), "=r"(r2), "=r"(r3) : "r"(addr));
}

__device__ __forceinline__ uint32_t smem_u32(const void* p) {
    uint32_t a;
    asm("{ .reg .u64 t; cvta.to.shared.u64 t, %1; cvt.u32.u64 %0, t; }"
        : "=r"(a) : "l"(p));
    return a;
}

__device__ __forceinline__ void cp_async16(uint32_t dst, const void* src) {
    asm volatile("cp.async.cg.shared.global [%0], [%1], 16;" :: "r"(dst), "l"(src));
}
#define CP_COMMIT() asm volatile("cp.async.commit_group;" ::: "memory")
#define CP_WAIT0()  asm volatile("cp.async.wait_group 0;" ::: "memory")
#define CP_WAIT1()  asm volatile("cp.async.wait_group 1;" ::: "memory")

// ============================================================
// RoPE tables
// ============================================================
__global__ void rope_tables_kernel() {
    int idx = blockIdx.x * blockDim.x + threadIdx.x;
    if (idx >= NT * 64) return;
    int t = idx >> 6;
    int i = idx & 63;
    double inv_f = exp(-((double)i / 64.0) * log(1.0e6));
    double ang = (double)t * inv_f;
    g_cos[idx] = (float)cos(ang);
    g_sin[idx] = (float)sin(ang);
}

// ============================================================
// tf32-round copy
// ============================================================
__global__ __launch_bounds__(256) void cvt_copy_kernel(
    const float4* __restrict__ in, float4* __restrict__ out, int n4)
{
    int i = blockIdx.x * blockDim.x + threadIdx.x;
    if (i >= n4) return;
    float4 v = in[i];
    v.x = tf32r(v.x); v.y = tf32r(v.y); v.z = tf32r(v.z); v.w = tf32r(v.w);
    out[i] = v;
}

// ============================================================
// Transpose + tf32 round
// ============================================================
__global__ __launch_bounds__(256) void transpose_kernel(
    const float* __restrict__ in, float* __restrict__ out, int R, int Ccols)
{
    __shared__ float tile[32][33];
    int c0 = blockIdx.x * 32, r0 = blockIdx.y * 32;
    int tx = threadIdx.x, ty = threadIdx.y;
#pragma unroll
    for (int j = 0; j < 32; j += 8)
        tile[ty + j][tx] = in[(size_t)(r0 + ty + j) * Ccols + c0 + tx];
    __syncthreads();
#pragma unroll
    for (int j = 0; j < 32; j += 8)
        out[(size_t)(c0 + ty + j) * R + r0 + tx] = tf32r(tile[tx][ty + j]);
}

// ============================================================
// tf32 mma GEMM v4 (= R5 config + ldmatrix frags, no trailing barrier)
// Block 128x256, BK=32, 256 thr = 8 warps (2m x 4n), warp 64x64,
// 3-stage cp.async ring.
// ============================================================
#define G4_BM 128
#define G4_BN 256
#define G4_STG_FLOATS 13824
#define G4_STG_BYTES  55296
#define G4_SMEM_BYTES (3 * G4_STG_BYTES)

__global__ __launch_bounds__(256, 1) void gemm_mma4_kernel(
    const float* __restrict__ A, const float* __restrict__ Bt,
    float* __restrict__ Cm, int M, int N, int K)
{
    extern __shared__ float sm[];
    const uint32_t smb = smem_u32(sm);

    const int tid = threadIdx.x;
    const int wid = tid >> 5;
    const int lane = tid & 31;
    const int gid = lane >> 2;
    const int tig = lane & 3;
    const int warp_m = wid & 1;
    const int warp_n = wid >> 1;
    const int m0 = blockIdx.y << 7;
    const int n0 = blockIdx.x << 8;

    const int ar = tid >> 3;
    const int ak = (tid & 7) << 2;

    // ldmatrix lane geometry
    const int lrA = (((lane >> 3) & 1) << 3) + (lane & 7);  // A-quadrants: rowgrp then half
    const int lhA = (lane >> 4) & 1;
    const int lrB = (lane & 7) + (((lane >> 4) & 1) << 3);  // B-quadrants: half then pairgrp
    const int lhB = (lane >> 3) & 1;

    const int mbase = warp_m << 6;
    const int nbase = warp_n << 6;

    uint32_t aoff[4], boff[4];
#pragma unroll
    for (int mf = 0; mf < 4; mf++)
        aoff[mf] = (uint32_t)(((mbase + (mf << 4) + lrA) * 36 + lhA * 4) << 2);
#pragma unroll
    for (int np = 0; np < 4; np++)
        boff[np] = 18432u + (uint32_t)(((nbase + (np << 4) + lrB) * 36 + lhB * 4) << 2);

    float acc[4][8][4];
#pragma unroll
    for (int i = 0; i < 4; i++)
#pragma unroll
        for (int j = 0; j < 8; j++)
#pragma unroll
            for (int e = 0; e < 4; e++) acc[i][j][e] = 0.0f;

    const int nt = K >> 5;

#define G4_ISSUE(t_)                                                          \
    do {                                                                      \
        const int _k0 = (t_) << 5;                                            \
        const uint32_t _sb = smb + ((t_) % 3) * G4_STG_BYTES;                 \
        _Pragma("unroll")                                                     \
        for (int _i = 0; _i < 4; _i++) {                                      \
            int _r = ar + (_i << 5);                                          \
            cp_async16(_sb + (_r * 36 + ak) * 4,                              \
                       A + (size_t)(m0 + _r) * K + _k0 + ak);                 \
        }                                                                     \
        _Pragma("unroll")                                                     \
        for (int _i = 0; _i < 8; _i++) {                                      \
            int _r = ar + (_i << 5);                                          \
            cp_async16(_sb + 18432 + (_r * 36 + ak) * 4,                      \
                       Bt + (size_t)(n0 + _r) * K + _k0 + ak);                \
        }                                                                     \
    } while (0)

    G4_ISSUE(0); CP_COMMIT();
    G4_ISSUE(1); CP_COMMIT();

    for (int t = 0; t < nt; t++) {
        CP_WAIT1();
        __syncthreads();
        if (t + 2 < nt) G4_ISSUE(t + 2);
        CP_COMMIT();

        const uint32_t sb = smb + (t % 3) * G4_STG_BYTES;
#pragma unroll
        for (int ks = 0; ks < 4; ks++) {
            const uint32_t kboff = (uint32_t)(ks << 5);  // 8 floats = 32 bytes
            uint32_t af[4][4];
#pragma unroll
            for (int mf = 0; mf < 4; mf++)
                ldsm_x4(af[mf][0], af[mf][1], af[mf][2], af[mf][3],
                        sb + aoff[mf] + kboff);
            uint32_t bf[8][2];
#pragma unroll
            for (int np = 0; np < 4; np++) {
                uint32_t b0, b1, b2, b3;
                ldsm_x4(b0, b1, b2, b3, sb + boff[np] + kboff);
                bf[2 * np][0] = b0; bf[2 * np][1] = b1;
                bf[2 * np + 1][0] = b2; bf[2 * np + 1][1] = b3;
            }
#pragma unroll
            for (int mf = 0; mf < 4; mf++)
#pragma unroll
                for (int nf = 0; nf < 8; nf++)
                    mma_tf32(acc[mf][nf], af[mf][0], af[mf][1], af[mf][2], af[mf][3],
                             bf[nf][0], bf[nf][1]);
        }
        // no trailing barrier: stage overwritten at iter t+1 was consumed at
        // iter t; all threads pass the top barrier of t+1 after compute(t).
    }
#undef G4_ISSUE

#pragma unroll
    for (int mf = 0; mf < 4; mf++) {
#pragma unroll
        for (int nf = 0; nf < 8; nf++) {
            int r0_ = m0 + mbase + (mf << 4) + gid;
            int c = n0 + nbase + (nf << 3) + (tig << 1);
            *(float2*)&Cm[(size_t)r0_ * N + c] = make_float2(acc[mf][nf][0], acc[mf][nf][1]);
            *(float2*)&Cm[(size_t)(r0_ + 8) * N + c] = make_float2(acc[mf][nf][2], acc[mf][nf][3]);
        }
    }
}

// ============================================================
// RMSNorm + RoPE in-place on q,k; tf32-round q,k,v.
// ============================================================
__global__ __launch_bounds__(256) void rmsrope_kernel(
    const float* __restrict__ qw, const float* __restrict__ kw)
{
    const int tok = blockIdx.x;
    const int t = tok & (NT - 1);
    const int warp = threadIdx.x >> 5;
    const int lane = threadIdx.x & 31;

    const float c0 = g_cos[t * 64 + lane];
    const float s0 = g_sin[t * 64 + lane];
    const float c1 = g_cos[t * 64 + 32 + lane];
    const float s1 = g_sin[t * 64 + 32 + lane];

#pragma unroll
    for (int s = 0; s < 4; s++) {
        int task = warp + (s << 3);
        int isK = task >> 4;
        int h = task & 15;
        const float* w = isK ? kw : qw;
        size_t rbase = (size_t)tok * C3 + (size_t)isK * 2048 + (size_t)h * ND;

        float x0 = g_qkv[rbase + lane];
        float x1 = g_qkv[rbase + lane + 32];
        float x2 = g_qkv[rbase + lane + 64];
        float x3 = g_qkv[rbase + lane + 96];

        float ss = x0 * x0 + x1 * x1 + x2 * x2 + x3 * x3;
#pragma unroll
        for (int off = 16; off > 0; off >>= 1)
            ss += __shfl_xor_sync(0xffffffffu, ss, off);
        float inv = 1.0f / sqrtf(ss * (1.0f / (float)ND) + RMS_EPS);

        float n0 = x0 * inv * w[lane];
        float n1 = x1 * inv * w[lane + 32];
        float n2 = x2 * inv * w[lane + 64];
        float n3 = x3 * inv * w[lane + 96];

        g_qkv[rbase + lane]       = tf32r(n0 * c0 - n2 * s0);
        g_qkv[rbase + lane + 32]  = tf32r(n1 * c1 - n3 * s1);
        g_qkv[rbase + lane + 64]  = tf32r(n2 * c0 + n0 * s0);
        g_qkv[rbase + lane + 96]  = tf32r(n3 * c1 + n1 * s1);
    }

    {
        float4* vsec = (float4*)&g_qkv[(size_t)tok * C3 + 4096];
#pragma unroll
        for (int i = 0; i < 2; i++) {
            int idx = threadIdx.x + (i << 8);
            float4 v = vsec[idx];
            v.x = tf32r(v.x); v.y = tf32r(v.y); v.z = tf32r(v.z); v.w = tf32r(v.w);
            vsec[idx] = v;
        }
    }
}

// ============================================================
// Flash attention, tf32 mma + ldmatrix fragment loads.
// ============================================================
#define FK_QS   0
#define FK_STG  17152
#define FK_KS(s) (8448 + (s) * FK_STG)
#define FK_VS(s) (8448 + (s) * FK_STG + 8448)
#define FK_PS   42752
#define FK_RM   47104
#define FK_RS   47232
#define FK_FLOATS 47360
#define FK_SMEM_BYTES (FK_FLOATS * 4)

__global__ __launch_bounds__(256, 1) void flash_mma_kernel()
{
    extern __shared__ float sm[];
    const uint32_t smb = smem_u32(sm);

    const int tid = threadIdx.x;
    const int lane = tid & 31;
    const int wid = tid >> 5;
    const int gid = lane >> 2;
    const int tig = lane & 3;
    const int wm = wid & 3;
    const int wn = wid >> 2;
    const int mbase = wm << 4;

    // long q-blocks first (tail balance)
    const int qb = (int)gridDim.x - 1 - (int)blockIdx.x;
    const int bh = blockIdx.y;
    const int b = bh >> 4;
    const int h = bh & 15;
    const int q0 = qb << 6;

    // ldmatrix lane geometry
    const int lrA = (((lane >> 3) & 1) << 3) + (lane & 7);
    const int lhA = (lane >> 4) & 1;
    const int lrB = (lane & 7) + (((lane >> 4) & 1) << 3);
    const int lhB = (lane >> 3) & 1;

    const uint32_t qoff = smb + (uint32_t)((((mbase + lrA) * 132) + lhA * 4) << 2);
    const uint32_t poff = smb + (uint32_t)((FK_PS + (mbase + lrA) * 68 + lhA * 4) << 2);
    uint32_t koff[2];
#pragma unroll
    for (int jp = 0; jp < 2; jp++)
        koff[jp] = (uint32_t)((((wn << 5) + (jp << 4) + lrB) * 132 + lhB * 4) << 2);

    const size_t base = (size_t)b * NT * C3 + (size_t)h * ND;

#pragma unroll
    for (int i = 0; i < 8; i++) {
        int f = tid + (i << 8);
        int r = f >> 5;
        int d4 = (f & 31) << 2;
        float4 v = *(const float4*)&g_qkv[base + (size_t)(q0 + r) * C3 + d4];
        *(float4*)&sm[FK_QS + r * 132 + d4] = v;
    }

    {
        const int k0 = 0, bufi = 0;
#pragma unroll
        for (int i = 0; i < 8; i++) {
            int f = tid + (i << 8);
            int r = f >> 5;
            int d4 = (f & 31) << 2;
            const float* srcK = &g_qkv[base + (size_t)(k0 + r) * C3 + 2048 + d4];
            const float* srcV = &g_qkv[base + (size_t)(k0 + r) * C3 + 4096 + d4];
            cp_async16(smb + (FK_KS(bufi) + r * 132 + d4) * 4, srcK);
            cp_async16(smb + (FK_VS(bufi) + r * 136 + d4) * 4, srcV);
        }
        CP_COMMIT();
    }

    float o[8][4];
#pragma unroll
    for (int j = 0; j < 8; j++)
#pragma unroll
        for (int e = 0; e < 4; e++) o[j][e] = 0.0f;
    float m0_ = -INFINITY, m1_ = -INFINITY, l0_ = 0.0f, l1_ = 0.0f;

    const uint32_t* Vu0 = (const uint32_t*)(sm);
    float* Pf = sm + FK_PS;
    float* redm = sm + FK_RM;
    float* reds = sm + FK_RS;

    for (int kt = 0; kt <= qb; kt++) {
        CP_WAIT0();
        __syncthreads();
        if (kt < qb) {
            const int k0n = (kt + 1) << 6;
            const int bufn = (kt + 1) & 1;
#pragma unroll
            for (int i = 0; i < 8; i++) {
                int f = tid + (i << 8);
                int r = f >> 5;
                int d4 = (f & 31) << 2;
                const float* srcK = &g_qkv[base + (size_t)(k0n + r) * C3 + 2048 + d4];
                const float* srcV = &g_qkv[base + (size_t)(k0n + r) * C3 + 4096 + d4];
                cp_async16(smb + (FK_KS(bufn) + r * 132 + d4) * 4, srcK);
                cp_async16(smb + (FK_VS(bufn) + r * 136 + d4) * 4, srcV);
            }
            CP_COMMIT();
        }

        const int bufi = kt & 1;
        const uint32_t kbase = smb + (uint32_t)(FK_KS(bufi) << 2);
        const uint32_t* Vu = Vu0 + FK_VS(bufi);
        const int k0 = kt << 6;

        float s[4][4];
#pragma unroll
        for (int j = 0; j < 4; j++)
#pragma unroll
            for (int e = 0; e < 4; e++) s[j][e] = 0.0f;

#pragma unroll
        for (int kb = 0; kb < 128; kb += 8) {
            uint32_t a0, a1, a2, a3;
            ldsm_x4(a0, a1, a2, a3, qoff + (kb << 2));
#pragma unroll
            for (int jp = 0; jp < 2; jp++) {
                uint32_t b0, b1, b2, b3;
                ldsm_x4(b0, b1, b2, b3, kbase + koff[jp] + (kb << 2));
                mma_tf32(s[2 * jp],     a0, a1, a2, a3, b0, b1);
                mma_tf32(s[2 * jp + 1], a0, a1, a2, a3, b2, b3);
            }
        }

        const int r0g = q0 + mbase + gid;
        const int r1g = r0g + 8;
        if (kt == qb) {
#pragma unroll
            for (int j = 0; j < 4; j++) {
                int cbase = k0 + (wn << 5) + (j << 3) + (tig << 1);
                s[j][0] = (cbase     <= r0g) ? s[j][0] * SM_SCALE : -1e30f;
                s[j][1] = (cbase + 1 <= r0g) ? s[j][1] * SM_SCALE : -1e30f;
                s[j][2] = (cbase     <= r1g) ? s[j][2] * SM_SCALE : -1e30f;
                s[j][3] = (cbase + 1 <= r1g) ? s[j][3] * SM_SCALE : -1e30f;
            }
        } else {
#pragma unroll
            for (int j = 0; j < 4; j++) {
                s[j][0] *= SM_SCALE; s[j][1] *= SM_SCALE;
                s[j][2] *= SM_SCALE; s[j][3] *= SM_SCALE;
            }
        }

        float pm0 = fmaxf(fmaxf(s[0][0], s[0][1]), fmaxf(s[1][0], s[1][1]));
        pm0 = fmaxf(pm0, fmaxf(fmaxf(s[2][0], s[2][1]), fmaxf(s[3][0], s[3][1])));
        float pm1 = fmaxf(fmaxf(s[0][2], s[0][3]), fmaxf(s[1][2], s[1][3]));
        pm1 = fmaxf(pm1, fmaxf(fmaxf(s[2][2], s[2][3]), fmaxf(s[3][2], s[3][3])));
        pm0 = fmaxf(pm0, __shfl_xor_sync(0xffffffffu, pm0, 1));
        pm0 = fmaxf(pm0, __shfl_xor_sync(0xffffffffu, pm0, 2));
        pm1 = fmaxf(pm1, __shfl_xor_sync(0xffffffffu, pm1, 1));
        pm1 = fmaxf(pm1, __shfl_xor_sync(0xffffffffu, pm1, 2));
        if (tig == 0) {
            redm[(wn << 6) + mbase + gid] = pm0;
            redm[(wn << 6) + mbase + gid + 8] = pm1;
        }
        __syncthreads();
        float mn0 = fmaxf(m0_, fmaxf(pm0, redm[((wn ^ 1) << 6) + mbase + gid]));
        float mn1 = fmaxf(m1_, fmaxf(pm1, redm[((wn ^ 1) << 6) + mbase + gid + 8]));
        float corr0 = __expf(m0_ - mn0);
        float corr1 = __expf(m1_ - mn1);

        float ps0 = 0.0f, ps1 = 0.0f;
#pragma unroll
        for (int j = 0; j < 4; j++) {
            float p00 = __expf(s[j][0] - mn0);
            float p01 = __expf(s[j][1] - mn0);
            float p10 = __expf(s[j][2] - mn1);
            float p11 = __expf(s[j][3] - mn1);
            ps0 += p00 + p01;
            ps1 += p10 + p11;
            int c = (wn << 5) + (j << 3) + (tig << 1);
            *(float2*)&Pf[(mbase + gid) * 68 + c] = make_float2(tf32r(p00), tf32r(p01));
            *(float2*)&Pf[(mbase + gid + 8) * 68 + c] = make_float2(tf32r(p10), tf32r(p11));
        }
        ps0 += __shfl_xor_sync(0xffffffffu, ps0, 1);
        ps0 += __shfl_xor_sync(0xffffffffu, ps0, 2);
        ps1 += __shfl_xor_sync(0xffffffffu, ps1, 1);
        ps1 += __shfl_xor_sync(0xffffffffu, ps1, 2);
        if (tig == 0) {
            reds[(wn << 6) + mbase + gid] = ps0;
            reds[(wn << 6) + mbase + gid + 8] = ps1;
        }
        __syncthreads();
        l0_ = l0_ * corr0 + ps0 + reds[((wn ^ 1) << 6) + mbase + gid];
        l1_ = l1_ * corr1 + ps1 + reds[((wn ^ 1) << 6) + mbase + gid + 8];
        m0_ = mn0; m1_ = mn1;
#pragma unroll
        for (int j = 0; j < 8; j++) {
            o[j][0] *= corr0; o[j][1] *= corr0;
            o[j][2] *= corr1; o[j][3] *= corr1;
        }

#pragma unroll
        for (int kb = 0; kb < 64; kb += 8) {
            uint32_t a0, a1, a2, a3;
            ldsm_x4(a0, a1, a2, a3, poff + (kb << 2));
#pragma unroll
            for (int j = 0; j < 8; j++) {
                int dcol = (wn << 6) + (j << 3) + gid;
                uint32_t b0 = Vu[(kb + tig) * 136 + dcol];
                uint32_t b1 = Vu[(kb + tig + 4) * 136 + dcol];
                mma_tf32(o[j], a0, a1, a2, a3, b0, b1);
            }
        }
    }

    const float inv0 = 1.0f / l0_;
    const float inv1 = 1.0f / l1_;
    const int r0g = q0 + mbase + gid;
    const size_t y0 = ((size_t)b * NT + r0g) * NC + (size_t)h * ND;
    const size_t y1 = y0 + (size_t)8 * NC;
#pragma unroll
    for (int j = 0; j < 8; j++) {
        int c = (wn << 6) + (j << 3) + (tig << 1);
        *(float2*)&g_y[y0 + c] = make_float2(tf32r(o[j][0] * inv0), tf32r(o[j][1] * inv0));
        *(float2*)&g_y[y1 + c] = make_float2(tf32r(o[j][2] * inv1), tf32r(o[j][3] * inv1));
    }
}

// ============================================================
// launch
// ============================================================
extern "C" void kernel_launch(void* const* d_in, const int* in_sizes, int n_in,
                              void* d_out, int out_size)
{
    const float* x      = (const float*)d_in[0];
    const float* w_qkv  = (const float*)d_in[1];
    const float* w_proj = (const float*)d_in[2];
    const float* qw     = (const float*)d_in[3];
    const float* kw     = (const float*)d_in[4];
    float* out = (float*)d_out;

    float* qkv_ptr = nullptr;
    float* y_ptr = nullptr;
    float* xt_ptr = nullptr;
    float* wqkvT_ptr = nullptr;
    float* wprojT_ptr = nullptr;
    cudaGetSymbolAddress((void**)&qkv_ptr, g_qkv);
    cudaGetSymbolAddress((void**)&y_ptr, g_y);
    cudaGetSymbolAddress((void**)&xt_ptr, g_xt);
    cudaGetSymbolAddress((void**)&wqkvT_ptr, g_wqkvT);
    cudaGetSymbolAddress((void**)&wprojT_ptr, g_wprojT);

    cudaFuncSetAttribute(gemm_mma4_kernel,
                         cudaFuncAttributeMaxDynamicSharedMemorySize, G4_SMEM_BYTES);
    cudaFuncSetAttribute(flash_mma_kernel,
                         cudaFuncAttributeMaxDynamicSharedMemorySize, FK_SMEM_BYTES);

    // 1. RoPE tables
    rope_tables_kernel<<<(NT * 64 + 255) / 256, 256>>>();

    // 2. tf32-rounded operands
    {
        int n4 = BT * NC / 4;
        cvt_copy_kernel<<<(n4 + 255) / 256, 256>>>((const float4*)x, (float4*)xt_ptr, n4);
        dim3 blk(32, 8);
        transpose_kernel<<<dim3(C3 / 32, NC / 32), blk>>>(w_qkv, wqkvT_ptr, NC, C3);
        transpose_kernel<<<dim3(NC / 32, NC / 32), blk>>>(w_proj, wprojT_ptr, NC, NC);
    }

    // 3. qkv = x @ w_qkv
    {
        dim3 grid(C3 / G4_BN, BT / G4_BM);
        gemm_mma4_kernel<<<grid, 256, G4_SMEM_BYTES>>>(xt_ptr, wqkvT_ptr, qkv_ptr, BT, C3, NC);
    }

    // 4. RMSNorm + RoPE
    rmsrope_kernel<<<BT, 256>>>(qw, kw);

    // 5. flash attention
    {
        dim3 grid(NT / 64, NB * NH);
        flash_mma_kernel<<<grid, 256, FK_SMEM_BYTES>>>();
    }

    // 6. out = y @ w_proj
    {
        dim3 grid(NC / G4_BN, BT / G4_BM);
        gemm_mma4_kernel<<<grid, 256, G4_SMEM_BYTES>>>(y_ptr, wprojT_ptr, out, BT, NC, NC);
    }
}

// round 10
// speedup vs baseline: 1.2747x; 1.2132x over previous
#include <cuda_runtime.h>
#include <cuda_bf16.h>
#include <math.h>
#include <stdint.h>

// ---------------- problem constants ----------------
#define NB 2
#define NT 2048
#define NC 2048
#define NH 16
#define ND 128
#define C3 (3 * NC)      /* 6144 */
#define BT (NB * NT)     /* 4096 */

#define RMS_EPS 1.1920929e-07f
#define SM_SCALE (1.0f / 128.0f)

// ---------------- scratch ----------------
__device__ float g_qkv[(size_t)BT * C3];          // fp32 qkv (q,k raw; v tf32-rounded)
__device__ float g_y[(size_t)BT * NC];
__device__ float g_xt[(size_t)BT * NC];           // x tf32-rounded (v-GEMM A)
__device__ float g_wqkvT[(size_t)C3 * NC];        // w_qkv^T tf32-rounded
__device__ float g_wprojT[(size_t)NC * NC];       // w_proj^T tf32-rounded
__device__ __nv_bfloat16 g_x16[(size_t)BT * NC];        // x bf16 (qk-GEMM A)
__device__ __nv_bfloat16 g_wqk16[(size_t)2 * NC * NC];  // w_qkv^T rows [0,4096) bf16
__device__ __nv_bfloat16 g_qk16[(size_t)BT * 2 * NC];   // [tok][{q,k}][h*128+d] bf16
__device__ float g_cos[NT * 64];
__device__ float g_sin[NT * 64];

// ---------------- helpers ----------------
__device__ __forceinline__ float tf32r(float x) {
    uint32_t o;
    asm("cvt.rna.tf32.f32 %0, %1;" : "=r"(o) : "f"(x));
    return __uint_as_float(o);
}

__device__ __forceinline__ void mma_tf32(float c[4],
                                         uint32_t a0, uint32_t a1, uint32_t a2, uint32_t a3,
                                         uint32_t b0, uint32_t b1) {
    asm volatile(
        "mma.sync.aligned.m16n8k8.row.col.f32.tf32.tf32.f32 "
        "{%0,%1,%2,%3}, {%4,%5,%6,%7}, {%8,%9}, {%0,%1,%2,%3};"
        : "+f"(c[0]), "+f"(c[1]), "+f"(c[2]), "+f"(c[3])
        : "r"(a0), "r"(a1), "r"(a2), "r"(a3), "r"(b0), "r"(b1));
}

__device__ __forceinline__ void mma_bf16(float c[4],
                                         uint32_t a0, uint32_t a1, uint32_t a2, uint32_t a3,
                                         uint32_t b0, uint32_t b1) {
    asm volatile(
        "mma.sync.aligned.m16n8k16.row.col.f32.bf16.bf16.f32 "
        "{%0,%1,%2,%3}, {%4,%5,%6,%7}, {%8,%9}, {%0,%1,%2,%3};"
        : "+f"(c[0]), "+f"(c[1]), "+f"(c[2]), "+f"(c[3])
        : "r"(a0), "r"(a1), "r"(a2), "r"(a3), "r"(b0), "r"(b1));
}

__device__ __forceinline__ void ldsm_x4(uint32_t& r0, uint32_t& r1,
                                        uint32_t& r2, uint32_t& r3, uint32_t addr) {
    asm volatile("ldmatrix.sync.aligned.m8n8.x4.shared.b16 {%0,%1,%2,%3}, [%4];"
        : "=r"(r0), "=r"(r1), "=r"(r2), "=r"(r3) : "r"(addr));
}

__device__ __forceinline__ uint32_t smem_u32(const void* p) {
    uint32_t a;
    asm("{ .reg .u64 t; cvta.to.shared.u64 t, %1; cvt.u32.u64 %0, t; }"
        : "=r"(a) : "l"(p));
    return a;
}

__device__ __forceinline__ void cp_async16(uint32_t dst, const void* src) {
    asm volatile("cp.async.cg.shared.global [%0], [%1], 16;" :: "r"(dst), "l"(src));
}
#define CP_COMMIT() asm volatile("cp.async.commit_group;" ::: "memory")
#define CP_WAIT0()  asm volatile("cp.async.wait_group 0;" ::: "memory")
#define CP_WAIT1()  asm volatile("cp.async.wait_group 1;" ::: "memory")

// ============================================================
// RoPE tables
// ============================================================
__global__ void rope_tables_kernel() {
    int idx = blockIdx.x * blockDim.x + threadIdx.x;
    if (idx >= NT * 64) return;
    int t = idx >> 6;
    int i = idx & 63;
    double inv_f = exp(-((double)i / 64.0) * log(1.0e6));
    double ang = (double)t * inv_f;
    g_cos[idx] = (float)cos(ang);
    g_sin[idx] = (float)sin(ang);
}

// ============================================================
// x -> tf32-rounded fp32 copy + bf16 copy
// ============================================================
__global__ __launch_bounds__(256) void cvt_dual_kernel(
    const float4* __restrict__ in, float4* __restrict__ out32,
    uint2* __restrict__ out16, int n4)
{
    int i = blockIdx.x * blockDim.x + threadIdx.x;
    if (i >= n4) return;
    float4 v = in[i];
    float4 r = make_float4(tf32r(v.x), tf32r(v.y), tf32r(v.z), tf32r(v.w));
    out32[i] = r;
    __nv_bfloat162 lo = __floats2bfloat162_rn(v.x, v.y);
    __nv_bfloat162 hi = __floats2bfloat162_rn(v.z, v.w);
    uint2 p;
    p.x = *(uint32_t*)&lo;
    p.y = *(uint32_t*)&hi;
    out16[i] = p;
}

// fp32 -> bf16 convert (for w_qkv^T q,k rows)
__global__ __launch_bounds__(256) void cvt16_kernel(
    const float4* __restrict__ in, uint2* __restrict__ out, int n4)
{
    int i = blockIdx.x * blockDim.x + threadIdx.x;
    if (i >= n4) return;
    float4 v = in[i];
    __nv_bfloat162 lo = __floats2bfloat162_rn(v.x, v.y);
    __nv_bfloat162 hi = __floats2bfloat162_rn(v.z, v.w);
    uint2 p;
    p.x = *(uint32_t*)&lo;
    p.y = *(uint32_t*)&hi;
    out[i] = p;
}

// ============================================================
// Transpose + tf32 round
// ============================================================
__global__ __launch_bounds__(256) void transpose_kernel(
    const float* __restrict__ in, float* __restrict__ out, int R, int Ccols)
{
    __shared__ float tile[32][33];
    int c0 = blockIdx.x * 32, r0 = blockIdx.y * 32;
    int tx = threadIdx.x, ty = threadIdx.y;
#pragma unroll
    for (int j = 0; j < 32; j += 8)
        tile[ty + j][tx] = in[(size_t)(r0 + ty + j) * Ccols + c0 + tx];
    __syncthreads();
#pragma unroll
    for (int j = 0; j < 32; j += 8)
        out[(size_t)(c0 + ty + j) * R + r0 + tx] = tf32r(tile[tx][ty + j]);
}

// ============================================================
// tf32 mma GEMM (v-GEMM + proj). Block 128x256, 256 thr, ldmatrix.
// Writes C[r*ldC + c0off + c].
// ============================================================
#define G4_STG_FLOATS 13824
#define G4_STG_BYTES  55296
#define G4_SMEM_BYTES (3 * G4_STG_BYTES)

__global__ __launch_bounds__(256, 1) void gemm_mma4_kernel(
    const float* __restrict__ A, const float* __restrict__ Bt,
    float* __restrict__ Cm, int K, int ldC, int c0off)
{
    extern __shared__ float sm[];
    const uint32_t smb = smem_u32(sm);

    const int tid = threadIdx.x;
    const int wid = tid >> 5;
    const int lane = tid & 31;
    const int gid = lane >> 2;
    const int tig = lane & 3;
    const int warp_m = wid & 1;
    const int warp_n = wid >> 1;
    const int m0 = blockIdx.y << 7;
    const int n0 = blockIdx.x << 8;

    const int ar = tid >> 3;
    const int ak = (tid & 7) << 2;

    const int lrA = (((lane >> 3) & 1) << 3) + (lane & 7);
    const int lhA = (lane >> 4) & 1;
    const int lrB = (lane & 7) + (((lane >> 4) & 1) << 3);
    const int lhB = (lane >> 3) & 1;

    const int mbase = warp_m << 6;
    const int nbase = warp_n << 6;

    uint32_t aoff[4], boff[4];
#pragma unroll
    for (int mf = 0; mf < 4; mf++)
        aoff[mf] = (uint32_t)(((mbase + (mf << 4) + lrA) * 36 + lhA * 4) << 2);
#pragma unroll
    for (int np = 0; np < 4; np++)
        boff[np] = 18432u + (uint32_t)(((nbase + (np << 4) + lrB) * 36 + lhB * 4) << 2);

    float acc[4][8][4];
#pragma unroll
    for (int i = 0; i < 4; i++)
#pragma unroll
        for (int j = 0; j < 8; j++)
#pragma unroll
            for (int e = 0; e < 4; e++) acc[i][j][e] = 0.0f;

    const int nt = K >> 5;

#define G4_ISSUE(t_)                                                          \
    do {                                                                      \
        const int _k0 = (t_) << 5;                                            \
        const uint32_t _sb = smb + ((t_) % 3) * G4_STG_BYTES;                 \
        _Pragma("unroll")                                                     \
        for (int _i = 0; _i < 4; _i++) {                                      \
            int _r = ar + (_i << 5);                                          \
            cp_async16(_sb + (_r * 36 + ak) * 4,                              \
                       A + (size_t)(m0 + _r) * K + _k0 + ak);                 \
        }                                                                     \
        _Pragma("unroll")                                                     \
        for (int _i = 0; _i < 8; _i++) {                                      \
            int _r = ar + (_i << 5);                                          \
            cp_async16(_sb + 18432 + (_r * 36 + ak) * 4,                      \
                       Bt + (size_t)(n0 + _r) * K + _k0 + ak);                \
        }                                                                     \
    } while (0)

    G4_ISSUE(0); CP_COMMIT();
    G4_ISSUE(1); CP_COMMIT();

    for (int t = 0; t < nt; t++) {
        CP_WAIT1();
        __syncthreads();
        if (t + 2 < nt) G4_ISSUE(t + 2);
        CP_COMMIT();

        const uint32_t sb = smb + (t % 3) * G4_STG_BYTES;
#pragma unroll
        for (int ks = 0; ks < 4; ks++) {
            const uint32_t kboff = (uint32_t)(ks << 5);
            uint32_t af[4][4];
#pragma unroll
            for (int mf = 0; mf < 4; mf++)
                ldsm_x4(af[mf][0], af[mf][1], af[mf][2], af[mf][3],
                        sb + aoff[mf] + kboff);
            uint32_t bf[8][2];
#pragma unroll
            for (int np = 0; np < 4; np++) {
                uint32_t b0, b1, b2, b3;
                ldsm_x4(b0, b1, b2, b3, sb + boff[np] + kboff);
                bf[2 * np][0] = b0; bf[2 * np][1] = b1;
                bf[2 * np + 1][0] = b2; bf[2 * np + 1][1] = b3;
            }
#pragma unroll
            for (int mf = 0; mf < 4; mf++)
#pragma unroll
                for (int nf = 0; nf < 8; nf++)
                    mma_tf32(acc[mf][nf], af[mf][0], af[mf][1], af[mf][2], af[mf][3],
                             bf[nf][0], bf[nf][1]);
        }
    }
#undef G4_ISSUE

#pragma unroll
    for (int mf = 0; mf < 4; mf++) {
#pragma unroll
        for (int nf = 0; nf < 8; nf++) {
            int r0_ = m0 + mbase + (mf << 4) + gid;
            int c = c0off + n0 + nbase + (nf << 3) + (tig << 1);
            *(float2*)&Cm[(size_t)r0_ * ldC + c] = make_float2(acc[mf][nf][0], acc[mf][nf][1]);
            *(float2*)&Cm[(size_t)(r0_ + 8) * ldC + c] = make_float2(acc[mf][nf][2], acc[mf][nf][3]);
        }
    }
}

// ============================================================
// bf16 mma GEMM (qk part of qkv). Block 128x256, BK=32, 256 thr,
// 8 warps (2m x 4n), warp 64x64, m16n8k16, 3-stage cp.async.
// A: g_x16 [M][K] bf16; Bt: g_wqk16 [N][K] bf16. C fp32.
// smem/stage: A 128 rows * 80 B + B 256 rows * 80 B = 30720 B.
// ============================================================
#define GB_STG_BYTES 30720
#define GB_SMEM_BYTES (3 * GB_STG_BYTES)

__global__ __launch_bounds__(256, 1) void gemm_bf16_kernel(
    const __nv_bfloat16* __restrict__ A, const __nv_bfloat16* __restrict__ Bt,
    float* __restrict__ Cm, int K, int ldC, int c0off)
{
    extern __shared__ float sm[];
    const uint32_t smb = smem_u32(sm);

    const int tid = threadIdx.x;
    const int wid = tid >> 5;
    const int lane = tid & 31;
    const int gid = lane >> 2;
    const int tig = lane & 3;
    const int warp_m = wid & 1;
    const int warp_n = wid >> 1;
    const int m0 = blockIdx.y << 7;
    const int n0 = blockIdx.x << 8;

    const int mbase = warp_m << 6;
    const int nbase = warp_n << 6;

    // bf16 ldmatrix lane geometry (canonical)
    const int la16 = lane & 15;           // A: row within 16
    const int lha = lane >> 4;            // A: k-halfword segment (16B)
    const int lb8 = lane & 7;             // B: col within 8
    const int lbg = (lane >> 4) & 1;      // B: col group (+8)
    const int lbh = (lane >> 3) & 1;      // B: k segment

    uint32_t aoff[4], boff[4];
#pragma unroll
    for (int mf = 0; mf < 4; mf++)
        aoff[mf] = (uint32_t)((mbase + (mf << 4) + la16) * 80 + lha * 16);
#pragma unroll
    for (int g = 0; g < 4; g++)
        boff[g] = 10240u + (uint32_t)((nbase + (g << 4) + lb8 + (lbg << 3)) * 80 + lbh * 16);

    float acc[4][8][4];
#pragma unroll
    for (int i = 0; i < 4; i++)
#pragma unroll
        for (int j = 0; j < 8; j++)
#pragma unroll
            for (int e = 0; e < 4; e++) acc[i][j][e] = 0.0f;

    const int nt = K >> 5;   // 32 bf16 per chunk

#define GB_ISSUE(t_)                                                          \
    do {                                                                      \
        const int _k0 = (t_) << 5;                                            \
        const uint32_t _sb = smb + ((t_) % 3) * GB_STG_BYTES;                 \
        _Pragma("unroll")                                                     \
        for (int _i = 0; _i < 2; _i++) {                                      \
            int _f = tid + (_i << 8);                                         \
            int _r = _f >> 2, _s = _f & 3;                                    \
            cp_async16(_sb + _r * 80 + _s * 16,                               \
                (const char*)A + (((size_t)(m0 + _r) * K + _k0) << 1) + _s * 16); \
        }                                                                     \
        _Pragma("unroll")                                                     \
        for (int _i = 0; _i < 4; _i++) {                                      \
            int _f = tid + (_i << 8);                                         \
            int _r = _f >> 2, _s = _f & 3;                                    \
            cp_async16(_sb + 10240 + _r * 80 + _s * 16,                       \
                (const char*)Bt + (((size_t)(n0 + _r) * K + _k0) << 1) + _s * 16); \
        }                                                                     \
    } while (0)

    GB_ISSUE(0); CP_COMMIT();
    GB_ISSUE(1); CP_COMMIT();

    for (int t = 0; t < nt; t++) {
        CP_WAIT1();
        __syncthreads();
        if (t + 2 < nt) GB_ISSUE(t + 2);
        CP_COMMIT();

        const uint32_t sb = smb + (t % 3) * GB_STG_BYTES;
#pragma unroll
        for (int c = 0; c < 2; c++) {           // two k16 sub-chunks
            const uint32_t cb = (uint32_t)(c << 5);   // 16 bf16 = 32 B
            uint32_t af[4][4];
#pragma unroll
            for (int mf = 0; mf < 4; mf++)
                ldsm_x4(af[mf][0], af[mf][1], af[mf][2], af[mf][3],
                        sb + aoff[mf] + cb);
            uint32_t bf[8][2];
#pragma unroll
            for (int g = 0; g < 4; g++) {
                uint32_t b0, b1, b2, b3;
                ldsm_x4(b0, b1, b2, b3, sb + boff[g] + cb);
                bf[2 * g][0] = b0; bf[2 * g][1] = b1;
                bf[2 * g + 1][0] = b2; bf[2 * g + 1][1] = b3;
            }
#pragma unroll
            for (int mf = 0; mf < 4; mf++)
#pragma unroll
                for (int nf = 0; nf < 8; nf++)
                    mma_bf16(acc[mf][nf], af[mf][0], af[mf][1], af[mf][2], af[mf][3],
                             bf[nf][0], bf[nf][1]);
        }
    }
#undef GB_ISSUE

#pragma unroll
    for (int mf = 0; mf < 4; mf++) {
#pragma unroll
        for (int nf = 0; nf < 8; nf++) {
            int r0_ = m0 + mbase + (mf << 4) + gid;
            int c = c0off + n0 + nbase + (nf << 3) + (tig << 1);
            *(float2*)&Cm[(size_t)r0_ * ldC + c] = make_float2(acc[mf][nf][0], acc[mf][nf][1]);
            *(float2*)&Cm[(size_t)(r0_ + 8) * ldC + c] = make_float2(acc[mf][nf][2], acc[mf][nf][3]);
        }
    }
}

// ============================================================
// RMSNorm + RoPE: reads fp32 q,k from g_qkv, writes bf16 q,k to
// g_qk16; tf32-rounds v in place.
// ============================================================
__global__ __launch_bounds__(256) void rmsrope_kernel(
    const float* __restrict__ qw, const float* __restrict__ kw)
{
    const int tok = blockIdx.x;
    const int t = tok & (NT - 1);
    const int warp = threadIdx.x >> 5;
    const int lane = threadIdx.x & 31;

    const float c0 = g_cos[t * 64 + lane];
    const float s0 = g_sin[t * 64 + lane];
    const float c1 = g_cos[t * 64 + 32 + lane];
    const float s1 = g_sin[t * 64 + 32 + lane];

#pragma unroll
    for (int s = 0; s < 4; s++) {
        int task = warp + (s << 3);
        int isK = task >> 4;
        int h = task & 15;
        const float* w = isK ? kw : qw;
        size_t rbase = (size_t)tok * C3 + (size_t)isK * 2048 + (size_t)h * ND;

        float x0 = g_qkv[rbase + lane];
        float x1 = g_qkv[rbase + lane + 32];
        float x2 = g_qkv[rbase + lane + 64];
        float x3 = g_qkv[rbase + lane + 96];

        float ss = x0 * x0 + x1 * x1 + x2 * x2 + x3 * x3;
#pragma unroll
        for (int off = 16; off > 0; off >>= 1)
            ss += __shfl_xor_sync(0xffffffffu, ss, off);
        float inv = 1.0f / sqrtf(ss * (1.0f / (float)ND) + RMS_EPS);

        float n0 = x0 * inv * w[lane];
        float n1 = x1 * inv * w[lane + 32];
        float n2 = x2 * inv * w[lane + 64];
        float n3 = x3 * inv * w[lane + 96];

        float y0 = n0 * c0 - n2 * s0;
        float y1 = n1 * c1 - n3 * s1;
        float y2 = n2 * c0 + n0 * s0;
        float y3 = n3 * c1 + n1 * s1;

        __nv_bfloat16* dst = g_qk16 + ((size_t)tok * 2 + isK) * 2048 + h * ND;
        dst[lane]      = __float2bfloat16(y0);
        dst[lane + 32] = __float2bfloat16(y1);
        dst[lane + 64] = __float2bfloat16(y2);
        dst[lane + 96] = __float2bfloat16(y3);
    }

    {
        float4* vsec = (float4*)&g_qkv[(size_t)tok * C3 + 4096];
#pragma unroll
        for (int i = 0; i < 2; i++) {
            int idx = threadIdx.x + (i << 8);
            float4 v = vsec[idx];
            v.x = tf32r(v.x); v.y = tf32r(v.y); v.z = tf32r(v.z); v.w = tf32r(v.w);
            vsec[idx] = v;
        }
    }
}

// ============================================================
// Flash attention: bf16 S-phase (Q,K bf16, m16n8k16), tf32 PV.
// Byte layout (dyn smem):
//   Q  bf16 64x136      @ 0       (17408)
//   K  bf16 64x136 x2   @ 17408 + s*52224
//   V  f32  64x136 x2   @ 17408 + s*52224 + 17408 (34816)
//   P  f32  64x68       @ 121856  (17408)
//   RM f32 128          @ 139264
//   RS f32 128          @ 139776   total 140288
// ============================================================
#define FB_Q     0
#define FB_STG   52224
#define FB_K(s)  (17408 + (s) * FB_STG)
#define FB_V(s)  (17408 + (s) * FB_STG + 17408)
#define FB_P     121856
#define FB_RM    139264
#define FB_RS    139776
#define FB_SMEM_BYTES 140288

__global__ __launch_bounds__(256, 1) void flash_mma_kernel()
{
    extern __shared__ float sm[];
    char* smc = (char*)sm;
    const uint32_t smb = smem_u32(sm);

    const int tid = threadIdx.x;
    const int lane = tid & 31;
    const int wid = tid >> 5;
    const int gid = lane >> 2;
    const int tig = lane & 3;
    const int wm = wid & 3;
    const int wn = wid >> 2;
    const int mbase = wm << 4;

    const int qb = (int)gridDim.x - 1 - (int)blockIdx.x;   // long blocks first
    const int bh = blockIdx.y;
    const int b = bh >> 4;
    const int h = bh & 15;
    const int q0 = qb << 6;

    // bf16 ldsm lane geometry
    const int la16 = lane & 15;
    const int lha = lane >> 4;
    const int lb8 = lane & 7;
    const int lbg = (lane >> 4) & 1;
    const int lbh = (lane >> 3) & 1;

    const uint32_t qoff = smb + FB_Q + (uint32_t)((mbase + la16) * 272 + lha * 16);
    uint32_t koff[2];
#pragma unroll
    for (int g = 0; g < 2; g++)
        koff[g] = (uint32_t)(((wn << 5) + (g << 4) + lb8 + (lbg << 3)) * 272 + lbh * 16);

    // b32 ldsm trick for P (fp32, stride 68 floats) — unchanged from R8
    const int lrA32 = (((lane >> 3) & 1) << 3) + (lane & 7);
    const int lhA32 = (lane >> 4) & 1;
    const uint32_t poff = smb + FB_P + (uint32_t)(((mbase + lrA32) * 68 + lhA32 * 4) << 2);

    const size_t vbase = (size_t)b * NT * C3 + (size_t)h * ND + 4096;
    const __nv_bfloat16* qsrc = g_qk16 + ((size_t)(b * NT) * 2) * 2048 + h * ND;

    // ---- prologue: Q (bf16) + K0 (bf16) + V0 (f32) via cp.async ----
#pragma unroll
    for (int i = 0; i < 4; i++) {
        int f = tid + (i << 8);
        int r = f >> 4;          // 0..63
        int seg = f & 15;        // 16B segment within 256B row
        const char* srcQ = (const char*)(qsrc + (size_t)(q0 + r) * 2 * 2048) + seg * 16;
        cp_async16(smb + FB_Q + r * 272 + seg * 16, srcQ);
        const char* srcK = (const char*)(qsrc + 2048 + (size_t)r * 2 * 2048) + seg * 16;
        cp_async16(smb + FB_K(0) + r * 272 + seg * 16, srcK);
    }
#pragma unroll
    for (int i = 0; i < 8; i++) {
        int f = tid + (i << 8);
        int r = f >> 5;
        int d4 = (f & 31) << 2;
        cp_async16(smb + FB_V(0) + r * 544 + d4 * 4, &g_qkv[vbase + (size_t)r * C3 + d4]);
    }
    CP_COMMIT();

    float o[8][4];
#pragma unroll
    for (int j = 0; j < 8; j++)
#pragma unroll
        for (int e = 0; e < 4; e++) o[j][e] = 0.0f;
    float m0_ = -INFINITY, m1_ = -INFINITY, l0_ = 0.0f, l1_ = 0.0f;

    float* Pf = (float*)(smc + FB_P);
    float* redm = (float*)(smc + FB_RM);
    float* reds = (float*)(smc + FB_RS);

    for (int kt = 0; kt <= qb; kt++) {
        CP_WAIT0();
        __syncthreads();
        if (kt < qb) {
            const int k0n = (kt + 1) << 6;
            const int bufn = (kt + 1) & 1;
#pragma unroll
            for (int i = 0; i < 4; i++) {
                int f = tid + (i << 8);
                int r = f >> 4;
                int seg = f & 15;
                const char* srcK = (const char*)(qsrc + 2048 + (size_t)(k0n + r) * 2 * 2048) + seg * 16;
                cp_async16(smb + FB_K(bufn) + r * 272 + seg * 16, srcK);
            }
#pragma unroll
            for (int i = 0; i < 8; i++) {
                int f = tid + (i << 8);
                int r = f >> 5;
                int d4 = (f & 31) << 2;
                cp_async16(smb + FB_V(bufn) + r * 544 + d4 * 4,
                           &g_qkv[vbase + (size_t)(k0n + r) * C3 + d4]);
            }
            CP_COMMIT();
        }

        const int bufi = kt & 1;
        const uint32_t kstage = smb + FB_K(bufi);
        const uint32_t* Vu = (const uint32_t*)(smc + FB_V(bufi));
        const int k0 = kt << 6;

        // ---- S = Q @ K^T  (bf16, 8 k16-chunks) ----
        float s[4][4];
#pragma unroll
        for (int j = 0; j < 4; j++)
#pragma unroll
            for (int e = 0; e < 4; e++) s[j][e] = 0.0f;

#pragma unroll
        for (int c = 0; c < 8; c++) {
            const uint32_t cb = (uint32_t)(c << 5);   // 16 bf16 = 32 B
            uint32_t a0, a1, a2, a3;
            ldsm_x4(a0, a1, a2, a3, qoff + cb);
#pragma unroll
            for (int g = 0; g < 2; g++) {
                uint32_t b0, b1, b2, b3;
                ldsm_x4(b0, b1, b2, b3, kstage + koff[g] + cb);
                mma_bf16(s[2 * g],     a0, a1, a2, a3, b0, b1);
                mma_bf16(s[2 * g + 1], a0, a1, a2, a3, b2, b3);
            }
        }

        const int r0g = q0 + mbase + gid;
        const int r1g = r0g + 8;
        if (kt == qb) {
#pragma unroll
            for (int j = 0; j < 4; j++) {
                int cbase = k0 + (wn << 5) + (j << 3) + (tig << 1);
                s[j][0] = (cbase     <= r0g) ? s[j][0] * SM_SCALE : -1e30f;
                s[j][1] = (cbase + 1 <= r0g) ? s[j][1] * SM_SCALE : -1e30f;
                s[j][2] = (cbase     <= r1g) ? s[j][2] * SM_SCALE : -1e30f;
                s[j][3] = (cbase + 1 <= r1g) ? s[j][3] * SM_SCALE : -1e30f;
            }
        } else {
#pragma unroll
            for (int j = 0; j < 4; j++) {
                s[j][0] *= SM_SCALE; s[j][1] *= SM_SCALE;
                s[j][2] *= SM_SCALE; s[j][3] *= SM_SCALE;
            }
        }

        float pm0 = fmaxf(fmaxf(s[0][0], s[0][1]), fmaxf(s[1][0], s[1][1]));
        pm0 = fmaxf(pm0, fmaxf(fmaxf(s[2][0], s[2][1]), fmaxf(s[3][0], s[3][1])));
        float pm1 = fmaxf(fmaxf(s[0][2], s[0][3]), fmaxf(s[1][2], s[1][3]));
        pm1 = fmaxf(pm1, fmaxf(fmaxf(s[2][2], s[2][3]), fmaxf(s[3][2], s[3][3])));
        pm0 = fmaxf(pm0, __shfl_xor_sync(0xffffffffu, pm0, 1));
        pm0 = fmaxf(pm0, __shfl_xor_sync(0xffffffffu, pm0, 2));
        pm1 = fmaxf(pm1, __shfl_xor_sync(0xffffffffu, pm1, 1));
        pm1 = fmaxf(pm1, __shfl_xor_sync(0xffffffffu, pm1, 2));
        if (tig == 0) {
            redm[(wn << 6) + mbase + gid] = pm0;
            redm[(wn << 6) + mbase + gid + 8] = pm1;
        }
        __syncthreads();
        float mn0 = fmaxf(m0_, fmaxf(pm0, redm[((wn ^ 1) << 6) + mbase + gid]));
        float mn1 = fmaxf(m1_, fmaxf(pm1, redm[((wn ^ 1) << 6) + mbase + gid + 8]));
        float corr0 = __expf(m0_ - mn0);
        float corr1 = __expf(m1_ - mn1);

        float ps0 = 0.0f, ps1 = 0.0f;
#pragma unroll
        for (int j = 0; j < 4; j++) {
            float p00 = __expf(s[j][0] - mn0);
            float p01 = __expf(s[j][1] - mn0);
            float p10 = __expf(s[j][2] - mn1);
            float p11 = __expf(s[j][3] - mn1);
            ps0 += p00 + p01;
            ps1 += p10 + p11;
            int c = (wn << 5) + (j << 3) + (tig << 1);
            *(float2*)&Pf[(mbase + gid) * 68 + c] = make_float2(tf32r(p00), tf32r(p01));
            *(float2*)&Pf[(mbase + gid + 8) * 68 + c] = make_float2(tf32r(p10), tf32r(p11));
        }
        ps0 += __shfl_xor_sync(0xffffffffu, ps0, 1);
        ps0 += __shfl_xor_sync(0xffffffffu, ps0, 2);
        ps1 += __shfl_xor_sync(0xffffffffu, ps1, 1);
        ps1 += __shfl_xor_sync(0xffffffffu, ps1, 2);
        if (tig == 0) {
            reds[(wn << 6) + mbase + gid] = ps0;
            reds[(wn << 6) + mbase + gid + 8] = ps1;
        }
        __syncthreads();
        l0_ = l0_ * corr0 + ps0 + reds[((wn ^ 1) << 6) + mbase + gid];
        l1_ = l1_ * corr1 + ps1 + reds[((wn ^ 1) << 6) + mbase + gid + 8];
        m0_ = mn0; m1_ = mn1;
#pragma unroll
        for (int j = 0; j < 8; j++) {
            o[j][0] *= corr0; o[j][1] *= corr0;
            o[j][2] *= corr1; o[j][3] *= corr1;
        }

        // ---- O += P @ V (tf32, unchanged) ----
#pragma unroll
        for (int kb = 0; kb < 64; kb += 8) {
            uint32_t a0, a1, a2, a3;
            ldsm_x4(a0, a1, a2, a3, poff + (kb << 2));
#pragma unroll
            for (int j = 0; j < 8; j++) {
                int dcol = (wn << 6) + (j << 3) + gid;
                uint32_t b0 = Vu[(kb + tig) * 136 + dcol];
                uint32_t b1 = Vu[(kb + tig + 4) * 136 + dcol];
                mma_tf32(o[j], a0, a1, a2, a3, b0, b1);
            }
        }
    }

    const float inv0 = 1.0f / l0_;
    const float inv1 = 1.0f / l1_;
    const int r0g = q0 + mbase + gid;
    const size_t y0 = ((size_t)b * NT + r0g) * NC + (size_t)h * ND;
    const size_t y1 = y0 + (size_t)8 * NC;
#pragma unroll
    for (int j = 0; j < 8; j++) {
        int c = (wn << 6) + (j << 3) + (tig << 1);
        *(float2*)&g_y[y0 + c] = make_float2(tf32r(o[j][0] * inv0), tf32r(o[j][1] * inv0));
        *(float2*)&g_y[y1 + c] = make_float2(tf32r(o[j][2] * inv1), tf32r(o[j][3] * inv1));
    }
}

// ============================================================
// launch
// ============================================================
extern "C" void kernel_launch(void* const* d_in, const int* in_sizes, int n_in,
                              void* d_out, int out_size)
{
    const float* x      = (const float*)d_in[0];
    const float* w_qkv  = (const float*)d_in[1];
    const float* w_proj = (const float*)d_in[2];
    const float* qw     = (const float*)d_in[3];
    const float* kw     = (const float*)d_in[4];
    float* out = (float*)d_out;

    float* qkv_ptr = nullptr;
    float* y_ptr = nullptr;
    float* xt_ptr = nullptr;
    float* wqkvT_ptr = nullptr;
    float* wprojT_ptr = nullptr;
    __nv_bfloat16* x16_ptr = nullptr;
    __nv_bfloat16* wqk16_ptr = nullptr;
    cudaGetSymbolAddress((void**)&qkv_ptr, g_qkv);
    cudaGetSymbolAddress((void**)&y_ptr, g_y);
    cudaGetSymbolAddress((void**)&xt_ptr, g_xt);
    cudaGetSymbolAddress((void**)&wqkvT_ptr, g_wqkvT);
    cudaGetSymbolAddress((void**)&wprojT_ptr, g_wprojT);
    cudaGetSymbolAddress((void**)&x16_ptr, g_x16);
    cudaGetSymbolAddress((void**)&wqk16_ptr, g_wqk16);

    cudaFuncSetAttribute(gemm_mma4_kernel,
                         cudaFuncAttributeMaxDynamicSharedMemorySize, G4_SMEM_BYTES);
    cudaFuncSetAttribute(gemm_bf16_kernel,
                         cudaFuncAttributeMaxDynamicSharedMemorySize, GB_SMEM_BYTES);
    cudaFuncSetAttribute(flash_mma_kernel,
                         cudaFuncAttributeMaxDynamicSharedMemorySize, FB_SMEM_BYTES);

    // 1. RoPE tables
    rope_tables_kernel<<<(NT * 64 + 255) / 256, 256>>>();

    // 2. operand conversions
    {
        int n4 = BT * NC / 4;
        cvt_dual_kernel<<<(n4 + 255) / 256, 256>>>(
            (const float4*)x, (float4*)xt_ptr, (uint2*)x16_ptr, n4);
        dim3 blk(32, 8);
        transpose_kernel<<<dim3(C3 / 32, NC / 32), blk>>>(w_qkv, wqkvT_ptr, NC, C3);
        transpose_kernel<<<dim3(NC / 32, NC / 32), blk>>>(w_proj, wprojT_ptr, NC, NC);
        int n4b = 2 * NC * NC / 4;
        cvt16_kernel<<<(n4b + 255) / 256, 256>>>(
            (const float4*)wqkvT_ptr, (uint2*)wqk16_ptr, n4b);
    }

    // 3a. q,k = x @ w_qkv[:, 0:4096]  (bf16 mma)
    {
        dim3 grid(4096 / 256, BT / 128);
        gemm_bf16_kernel<<<grid, 256, GB_SMEM_BYTES>>>(
            x16_ptr, wqk16_ptr, qkv_ptr, NC, C3, 0);
    }
    // 3b. v = x @ w_qkv[:, 4096:6144]  (tf32 mma)
    {
        dim3 grid(2048 / 256, BT / 128);
        gemm_mma4_kernel<<<grid, 256, G4_SMEM_BYTES>>>(
            xt_ptr, wqkvT_ptr + (size_t)4096 * NC, qkv_ptr, NC, C3, 4096);
    }

    // 4. RMSNorm + RoPE -> bf16 q,k; tf32-round v
    rmsrope_kernel<<<BT, 256>>>(qw, kw);

    // 5. flash attention (bf16 S, tf32 PV)
    {
        dim3 grid(NT / 64, NB * NH);
        flash_mma_kernel<<<grid, 256, FB_SMEM_BYTES>>>();
    }

    // 6. out = y @ w_proj (tf32 mma)
    {
        dim3 grid(NC / 256, BT / 128);
        gemm_mma4_kernel<<<grid, 256, G4_SMEM_BYTES>>>(
            y_ptr, wprojT_ptr, out, NC, NC, 0);
    }
}

// round 12
// speedup vs baseline: 1.6928x; 1.3280x over previous
#include <cuda_runtime.h>
#include <cuda_fp16.h>
#include <math.h>
#include <stdint.h>

// ---------------- problem constants ----------------
#define NB 2
#define NT 2048
#define NC 2048
#define NH 16
#define ND 128
#define C3 (3 * NC)      /* 6144 */
#define BT (NB * NT)     /* 4096 */

#define RMS_EPS 1.1920929e-07f
#define SM_SCALE (1.0f / 128.0f)

// ---------------- scratch ----------------
__device__ float g_qkv[(size_t)BT * C3];           // fp32 qkv from GEMM
__device__ __half g_x16[(size_t)BT * NC];          // x fp16
__device__ __half g_wqkvT16[(size_t)C3 * NC];      // w_qkv^T fp16
__device__ __half g_wprojT16[(size_t)NC * NC];     // w_proj^T fp16
__device__ __half g_qk16[(size_t)BT * 2 * NC];     // [tok][{q,k}][h*128+d] fp16
__device__ __half g_v16[(size_t)BT * NC];          // v fp16
__device__ __half g_y16[(size_t)BT * NC];          // attention out fp16
__device__ float g_cos[NT * 64];
__device__ float g_sin[NT * 64];

// ---------------- helpers ----------------
__device__ __forceinline__ void mma_f16(float c[4],
                                        uint32_t a0, uint32_t a1, uint32_t a2, uint32_t a3,
                                        uint32_t b0, uint32_t b1) {
    asm volatile(
        "mma.sync.aligned.m16n8k16.row.col.f32.f16.f16.f32 "
        "{%0,%1,%2,%3}, {%4,%5,%6,%7}, {%8,%9}, {%0,%1,%2,%3};"
        : "+f"(c[0]), "+f"(c[1]), "+f"(c[2]), "+f"(c[3])
        : "r"(a0), "r"(a1), "r"(a2), "r"(a3), "r"(b0), "r"(b1));
}

__device__ __forceinline__ void ldsm_x4(uint32_t& r0, uint32_t& r1,
                                        uint32_t& r2, uint32_t& r3, uint32_t addr) {
    asm volatile("ldmatrix.sync.aligned.m8n8.x4.shared.b16 {%0,%1,%2,%3}, [%4];"
        : "=r"(r0), "=r"(r1), "=r"(r2), "=r"(r3) : "r"(addr));
}

__device__ __forceinline__ void ldsm_x4_trans(uint32_t& r0, uint32_t& r1,
                                              uint32_t& r2, uint32_t& r3, uint32_t addr) {
    asm volatile("ldmatrix.sync.aligned.m8n8.x4.trans.shared.b16 {%0,%1,%2,%3}, [%4];"
        : "=r"(r0), "=r"(r1), "=r"(r2), "=r"(r3) : "r"(addr));
}

__device__ __forceinline__ uint32_t smem_u32(const void* p) {
    uint32_t a;
    asm("{ .reg .u64 t; cvta.to.shared.u64 t, %1; cvt.u32.u64 %0, t; }"
        : "=r"(a) : "l"(p));
    return a;
}

__device__ __forceinline__ void cp_async16(uint32_t dst, const void* src) {
    asm volatile("cp.async.cg.shared.global [%0], [%1], 16;" :: "r"(dst), "l"(src));
}
#define CP_COMMIT() asm volatile("cp.async.commit_group;" ::: "memory")
#define CP_WAIT0()  asm volatile("cp.async.wait_group 0;" ::: "memory")
#define CP_WAIT1()  asm volatile("cp.async.wait_group 1;" ::: "memory")

// ============================================================
// RoPE tables
// ============================================================
__global__ void rope_tables_kernel() {
    int idx = blockIdx.x * blockDim.x + threadIdx.x;
    if (idx >= NT * 64) return;
    int t = idx >> 6;
    int i = idx & 63;
    double inv_f = exp(-((double)i / 64.0) * log(1.0e6));
    double ang = (double)t * inv_f;
    g_cos[idx] = (float)cos(ang);
    g_sin[idx] = (float)sin(ang);
}

// ============================================================
// fp32 -> fp16 copy
// ============================================================
__global__ __launch_bounds__(256) void cvt16_kernel(
    const float4* __restrict__ in, uint2* __restrict__ out, int n4)
{
    int i = blockIdx.x * blockDim.x + threadIdx.x;
    if (i >= n4) return;
    float4 v = in[i];
    __half2 lo = __floats2half2_rn(v.x, v.y);
    __half2 hi = __floats2half2_rn(v.z, v.w);
    uint2 p;
    p.x = *(uint32_t*)&lo;
    p.y = *(uint32_t*)&hi;
    out[i] = p;
}

// ============================================================
// Transpose -> fp16: out[C][R] = half(in[R][C])
// ============================================================
__global__ __launch_bounds__(256) void transpose16_kernel(
    const float* __restrict__ in, __half* __restrict__ out, int R, int Ccols)
{
    __shared__ float tile[32][33];
    int c0 = blockIdx.x * 32, r0 = blockIdx.y * 32;
    int tx = threadIdx.x, ty = threadIdx.y;
#pragma unroll
    for (int j = 0; j < 32; j += 8)
        tile[ty + j][tx] = in[(size_t)(r0 + ty + j) * Ccols + c0 + tx];
    __syncthreads();
#pragma unroll
    for (int j = 0; j < 32; j += 8)
        out[(size_t)(c0 + ty + j) * R + r0 + tx] = __float2half_rn(tile[tx][ty + j]);
}

// ============================================================
// fp16 mma GEMM: C[M,*] = A[M,K] @ Bt[N,K]^T (fp32 out).
// Block 128x256, BK=32, 256 thr (2m x 4n warps, warp 64x64),
// m16n8k16, 3-stage cp.async, ldmatrix frags.
// smem/stage: A 128*80 + B 256*80 = 30720 B.
// ============================================================
#define GB_STG_BYTES 30720
#define GB_SMEM_BYTES (3 * GB_STG_BYTES)

__global__ __launch_bounds__(256, 1) void gemm_f16_kernel(
    const __half* __restrict__ A, const __half* __restrict__ Bt,
    float* __restrict__ Cm, int K, int ldC, int c0off)
{
    extern __shared__ float sm[];
    const uint32_t smb = smem_u32(sm);

    const int tid = threadIdx.x;
    const int wid = tid >> 5;
    const int lane = tid & 31;
    const int gid = lane >> 2;
    const int tig = lane & 3;
    const int warp_m = wid & 1;
    const int warp_n = wid >> 1;
    const int m0 = blockIdx.y << 7;
    const int n0 = blockIdx.x << 8;

    const int mbase = warp_m << 6;
    const int nbase = warp_n << 6;

    const int la16 = lane & 15;
    const int lha = lane >> 4;
    const int lb8 = lane & 7;
    const int lbg = (lane >> 4) & 1;
    const int lbh = (lane >> 3) & 1;

    uint32_t aoff[4], boff[4];
#pragma unroll
    for (int mf = 0; mf < 4; mf++)
        aoff[mf] = (uint32_t)((mbase + (mf << 4) + la16) * 80 + lha * 16);
#pragma unroll
    for (int g = 0; g < 4; g++)
        boff[g] = 10240u + (uint32_t)((nbase + (g << 4) + lb8 + (lbg << 3)) * 80 + lbh * 16);

    float acc[4][8][4];
#pragma unroll
    for (int i = 0; i < 4; i++)
#pragma unroll
        for (int j = 0; j < 8; j++)
#pragma unroll
            for (int e = 0; e < 4; e++) acc[i][j][e] = 0.0f;

    const int nt = K >> 5;

#define GB_ISSUE(t_)                                                          \
    do {                                                                      \
        const int _k0 = (t_) << 5;                                            \
        const uint32_t _sb = smb + ((t_) % 3) * GB_STG_BYTES;                 \
        _Pragma("unroll")                                                     \
        for (int _i = 0; _i < 2; _i++) {                                      \
            int _f = tid + (_i << 8);                                         \
            int _r = _f >> 2, _s = _f & 3;                                    \
            cp_async16(_sb + _r * 80 + _s * 16,                               \
                (const char*)A + (((size_t)(m0 + _r) * K + _k0) << 1) + _s * 16); \
        }                                                                     \
        _Pragma("unroll")                                                     \
        for (int _i = 0; _i < 4; _i++) {                                      \
            int _f = tid + (_i << 8);                                         \
            int _r = _f >> 2, _s = _f & 3;                                    \
            cp_async16(_sb + 10240 + _r * 80 + _s * 16,                       \
                (const char*)Bt + (((size_t)(n0 + _r) * K + _k0) << 1) + _s * 16); \
        }                                                                     \
    } while (0)

    GB_ISSUE(0); CP_COMMIT();
    GB_ISSUE(1); CP_COMMIT();

    for (int t = 0; t < nt; t++) {
        CP_WAIT1();
        __syncthreads();
        if (t + 2 < nt) GB_ISSUE(t + 2);
        CP_COMMIT();

        const uint32_t sb = smb + (t % 3) * GB_STG_BYTES;
#pragma unroll
        for (int c = 0; c < 2; c++) {
            const uint32_t cb = (uint32_t)(c << 5);
            uint32_t af[4][4];
#pragma unroll
            for (int mf = 0; mf < 4; mf++)
                ldsm_x4(af[mf][0], af[mf][1], af[mf][2], af[mf][3],
                        sb + aoff[mf] + cb);
            uint32_t bf[8][2];
#pragma unroll
            for (int g = 0; g < 4; g++) {
                uint32_t b0, b1, b2, b3;
                ldsm_x4(b0, b1, b2, b3, sb + boff[g] + cb);
                bf[2 * g][0] = b0; bf[2 * g][1] = b1;
                bf[2 * g + 1][0] = b2; bf[2 * g + 1][1] = b3;
            }
#pragma unroll
            for (int mf = 0; mf < 4; mf++)
#pragma unroll
                for (int nf = 0; nf < 8; nf++)
                    mma_f16(acc[mf][nf], af[mf][0], af[mf][1], af[mf][2], af[mf][3],
                            bf[nf][0], bf[nf][1]);
        }
    }
#undef GB_ISSUE

#pragma unroll
    for (int mf = 0; mf < 4; mf++) {
#pragma unroll
        for (int nf = 0; nf < 8; nf++) {
            int r0_ = m0 + mbase + (mf << 4) + gid;
            int c = c0off + n0 + nbase + (nf << 3) + (tig << 1);
            *(float2*)&Cm[(size_t)r0_ * ldC + c] = make_float2(acc[mf][nf][0], acc[mf][nf][1]);
            *(float2*)&Cm[(size_t)(r0_ + 8) * ldC + c] = make_float2(acc[mf][nf][2], acc[mf][nf][3]);
        }
    }
}

// ============================================================
// RMSNorm + RoPE: fp32 q,k -> fp16 g_qk16; fp32 v -> fp16 g_v16.
// ============================================================
__global__ __launch_bounds__(256) void rmsrope_kernel(
    const float* __restrict__ qw, const float* __restrict__ kw)
{
    const int tok = blockIdx.x;
    const int t = tok & (NT - 1);
    const int warp = threadIdx.x >> 5;
    const int lane = threadIdx.x & 31;

    const float c0 = g_cos[t * 64 + lane];
    const float s0 = g_sin[t * 64 + lane];
    const float c1 = g_cos[t * 64 + 32 + lane];
    const float s1 = g_sin[t * 64 + 32 + lane];

#pragma unroll
    for (int s = 0; s < 4; s++) {
        int task = warp + (s << 3);
        int isK = task >> 4;
        int h = task & 15;
        const float* w = isK ? kw : qw;
        size_t rbase = (size_t)tok * C3 + (size_t)isK * 2048 + (size_t)h * ND;

        float x0 = g_qkv[rbase + lane];
        float x1 = g_qkv[rbase + lane + 32];
        float x2 = g_qkv[rbase + lane + 64];
        float x3 = g_qkv[rbase + lane + 96];

        float ss = x0 * x0 + x1 * x1 + x2 * x2 + x3 * x3;
#pragma unroll
        for (int off = 16; off > 0; off >>= 1)
            ss += __shfl_xor_sync(0xffffffffu, ss, off);
        float inv = 1.0f / sqrtf(ss * (1.0f / (float)ND) + RMS_EPS);

        float n0 = x0 * inv * w[lane];
        float n1 = x1 * inv * w[lane + 32];
        float n2 = x2 * inv * w[lane + 64];
        float n3 = x3 * inv * w[lane + 96];

        __half* dst = g_qk16 + ((size_t)tok * 2 + isK) * 2048 + h * ND;
        dst[lane]      = __float2half_rn(n0 * c0 - n2 * s0);
        dst[lane + 32] = __float2half_rn(n1 * c1 - n3 * s1);
        dst[lane + 64] = __float2half_rn(n2 * c0 + n0 * s0);
        dst[lane + 96] = __float2half_rn(n3 * c1 + n1 * s1);
    }

    // v: fp32 -> fp16
    {
        const float4* vsec = (const float4*)&g_qkv[(size_t)tok * C3 + 4096];
        uint2* vdst = (uint2*)(g_v16 + (size_t)tok * 2048);
#pragma unroll
        for (int i = 0; i < 2; i++) {
            int idx = threadIdx.x + (i << 8);
            float4 v = vsec[idx];
            __half2 lo = __floats2half2_rn(v.x, v.y);
            __half2 hi = __floats2half2_rn(v.z, v.w);
            uint2 p;
            p.x = *(uint32_t*)&lo;
            p.y = *(uint32_t*)&hi;
            vdst[idx] = p;
        }
    }
}

// ============================================================
// Flash attention, all-fp16 MMA (S and PV m16n8k16), fp32 softmax.
// smem bytes:
//   Q  h16 64x136        @ 0                  (17408)
//   K  h16 64x136 x2     @ 17408 + s*34816    (17408)
//   V  h16 64x136 x2     @ 17408 + s*34816 + 17408
//   P  h16 64x72         @ 87040              (9216)
//   RM f32 128           @ 96256, RS @ 96768   total 97280
// ============================================================
#define FB_Q     0
#define FB_STG   34816
#define FB_K(s)  (17408 + (s) * FB_STG)
#define FB_V(s)  (17408 + (s) * FB_STG + 17408)
#define FB_P     87040
#define FB_RM    96256
#define FB_RS    96768
#define FB_SMEM_BYTES 97280

__global__ __launch_bounds__(256, 2) void flash_mma_kernel()
{
    extern __shared__ float sm[];
    char* smc = (char*)sm;
    const uint32_t smb = smem_u32(sm);

    const int tid = threadIdx.x;
    const int lane = tid & 31;
    const int wid = tid >> 5;
    const int gid = lane >> 2;
    const int tig = lane & 3;
    const int wm = wid & 3;
    const int wn = wid >> 2;
    const int mbase = wm << 4;

    const int qb = (int)gridDim.x - 1 - (int)blockIdx.x;   // long blocks first
    const int bh = blockIdx.y;
    const int b = bh >> 4;
    const int h = bh & 15;
    const int q0 = qb << 6;

    // ldmatrix lane geometry (b16)
    const int la16 = lane & 15;
    const int lha = lane >> 4;
    const int lb8 = lane & 7;
    const int lbg = (lane >> 4) & 1;
    const int lbh = (lane >> 3) & 1;

    const uint32_t qoff = smb + FB_Q + (uint32_t)((mbase + la16) * 272 + lha * 16);
    uint32_t koff[2];
#pragma unroll
    for (int g = 0; g < 2; g++)
        koff[g] = (uint32_t)(((wn << 5) + (g << 4) + lb8 + (lbg << 3)) * 272 + lbh * 16);

    // P as A operand: [m][k] fp16, row stride 72 halfs = 144 B
    const uint32_t poff = smb + FB_P + (uint32_t)((mbase + la16) * 144 + lha * 16);

    // V as B operand via ldmatrix.trans: V stored [k][d], row stride 272 B
    const int vlk = (lane & 7) + (((lane >> 3) & 1) << 3);   // k within 16
    const int vln = ((lane >> 4) & 1) << 3;                  // n sub-offset
    uint32_t voff[4];
#pragma unroll
    for (int g = 0; g < 4; g++)
        voff[g] = (uint32_t)(vlk * 272 + ((wn << 6) + (g << 4) + vln) * 2);

    const __half* qk_base = g_qk16 + (size_t)(b * NT) * 4096 + h * ND;
    const __half* v_base = g_v16 + (size_t)(b * NT) * 2048 + h * ND;

    // ---- prologue: Q + K0 + V0 via cp.async (16B segs, 272B rows) ----
#pragma unroll
    for (int i = 0; i < 4; i++) {
        int f = tid + (i << 8);
        int r = f >> 4;
        int seg = f & 15;
        cp_async16(smb + FB_Q + r * 272 + seg * 16,
                   (const char*)(qk_base + (size_t)(q0 + r) * 4096) + seg * 16);
        cp_async16(smb + FB_K(0) + r * 272 + seg * 16,
                   (const char*)(qk_base + 2048 + (size_t)r * 4096) + seg * 16);
        cp_async16(smb + FB_V(0) + r * 272 + seg * 16,
                   (const char*)(v_base + (size_t)r * 2048) + seg * 16);
    }
    CP_COMMIT();

    float o[8][4];
#pragma unroll
    for (int j = 0; j < 8; j++)
#pragma unroll
        for (int e = 0; e < 4; e++) o[j][e] = 0.0f;
    float m0_ = -INFINITY, m1_ = -INFINITY, l0_ = 0.0f, l1_ = 0.0f;

    __half* Ph = (__half*)(smc + FB_P);
    float* redm = (float*)(smc + FB_RM);
    float* reds = (float*)(smc + FB_RS);

    for (int kt = 0; kt <= qb; kt++) {
        CP_WAIT0();
        __syncthreads();
        if (kt < qb) {
            const int k0n = (kt + 1) << 6;
            const int bufn = (kt + 1) & 1;
#pragma unroll
            for (int i = 0; i < 4; i++) {
                int f = tid + (i << 8);
                int r = f >> 4;
                int seg = f & 15;
                cp_async16(smb + FB_K(bufn) + r * 272 + seg * 16,
                           (const char*)(qk_base + 2048 + (size_t)(k0n + r) * 4096) + seg * 16);
                cp_async16(smb + FB_V(bufn) + r * 272 + seg * 16,
                           (const char*)(v_base + (size_t)(k0n + r) * 2048) + seg * 16);
            }
            CP_COMMIT();
        }

        const int bufi = kt & 1;
        const uint32_t kstage = smb + FB_K(bufi);
        const uint32_t vstage = smb + FB_V(bufi);
        const int k0 = kt << 6;

        // ---- S = Q @ K^T (fp16, 8 k16-chunks) ----
        float s[4][4];
#pragma unroll
        for (int j = 0; j < 4; j++)
#pragma unroll
            for (int e = 0; e < 4; e++) s[j][e] = 0.0f;

#pragma unroll
        for (int c = 0; c < 8; c++) {
            const uint32_t cb = (uint32_t)(c << 5);
            uint32_t a0, a1, a2, a3;
            ldsm_x4(a0, a1, a2, a3, qoff + cb);
#pragma unroll
            for (int g = 0; g < 2; g++) {
                uint32_t b0, b1, b2, b3;
                ldsm_x4(b0, b1, b2, b3, kstage + koff[g] + cb);
                mma_f16(s[2 * g],     a0, a1, a2, a3, b0, b1);
                mma_f16(s[2 * g + 1], a0, a1, a2, a3, b2, b3);
            }
        }

        const int r0g = q0 + mbase + gid;
        const int r1g = r0g + 8;
        if (kt == qb) {
#pragma unroll
            for (int j = 0; j < 4; j++) {
                int cbase = k0 + (wn << 5) + (j << 3) + (tig << 1);
                s[j][0] = (cbase     <= r0g) ? s[j][0] * SM_SCALE : -1e30f;
                s[j][1] = (cbase + 1 <= r0g) ? s[j][1] * SM_SCALE : -1e30f;
                s[j][2] = (cbase     <= r1g) ? s[j][2] * SM_SCALE : -1e30f;
                s[j][3] = (cbase + 1 <= r1g) ? s[j][3] * SM_SCALE : -1e30f;
            }
        } else {
#pragma unroll
            for (int j = 0; j < 4; j++) {
                s[j][0] *= SM_SCALE; s[j][1] *= SM_SCALE;
                s[j][2] *= SM_SCALE; s[j][3] *= SM_SCALE;
            }
        }

        // ---- online softmax (cross 2 n-warps via smem) ----
        float pm0 = fmaxf(fmaxf(s[0][0], s[0][1]), fmaxf(s[1][0], s[1][1]));
        pm0 = fmaxf(pm0, fmaxf(fmaxf(s[2][0], s[2][1]), fmaxf(s[3][0], s[3][1])));
        float pm1 = fmaxf(fmaxf(s[0][2], s[0][3]), fmaxf(s[1][2], s[1][3]));
        pm1 = fmaxf(pm1, fmaxf(fmaxf(s[2][2], s[2][3]), fmaxf(s[3][2], s[3][3])));
        pm0 = fmaxf(pm0, __shfl_xor_sync(0xffffffffu, pm0, 1));
        pm0 = fmaxf(pm0, __shfl_xor_sync(0xffffffffu, pm0, 2));
        pm1 = fmaxf(pm1, __shfl_xor_sync(0xffffffffu, pm1, 1));
        pm1 = fmaxf(pm1, __shfl_xor_sync(0xffffffffu, pm1, 2));
        if (tig == 0) {
            redm[(wn << 6) + mbase + gid] = pm0;
            redm[(wn << 6) + mbase + gid + 8] = pm1;
        }
        __syncthreads();
        float mn0 = fmaxf(m0_, fmaxf(pm0, redm[((wn ^ 1) << 6) + mbase + gid]));
        float mn1 = fmaxf(m1_, fmaxf(pm1, redm[((wn ^ 1) << 6) + mbase + gid + 8]));
        float corr0 = __expf(m0_ - mn0);
        float corr1 = __expf(m1_ - mn1);

        float ps0 = 0.0f, ps1 = 0.0f;
#pragma unroll
        for (int j = 0; j < 4; j++) {
            float p00 = __expf(s[j][0] - mn0);
            float p01 = __expf(s[j][1] - mn0);
            float p10 = __expf(s[j][2] - mn1);
            float p11 = __expf(s[j][3] - mn1);
            ps0 += p00 + p01;
            ps1 += p10 + p11;
            int c = (wn << 5) + (j << 3) + (tig << 1);
            *(__half2*)&Ph[(mbase + gid) * 72 + c] = __floats2half2_rn(p00, p01);
            *(__half2*)&Ph[(mbase + gid + 8) * 72 + c] = __floats2half2_rn(p10, p11);
        }
        ps0 += __shfl_xor_sync(0xffffffffu, ps0, 1);
        ps0 += __shfl_xor_sync(0xffffffffu, ps0, 2);
        ps1 += __shfl_xor_sync(0xffffffffu, ps1, 1);
        ps1 += __shfl_xor_sync(0xffffffffu, ps1, 2);
        if (tig == 0) {
            reds[(wn << 6) + mbase + gid] = ps0;
            reds[(wn << 6) + mbase + gid + 8] = ps1;
        }
        __syncthreads();
        l0_ = l0_ * corr0 + ps0 + reds[((wn ^ 1) << 6) + mbase + gid];
        l1_ = l1_ * corr1 + ps1 + reds[((wn ^ 1) << 6) + mbase + gid + 8];
        m0_ = mn0; m1_ = mn1;
#pragma unroll
        for (int j = 0; j < 8; j++) {
            o[j][0] *= corr0; o[j][1] *= corr0;
            o[j][2] *= corr1; o[j][3] *= corr1;
        }

        // ---- O += P @ V (fp16; V via ldmatrix.trans; 4 k16-chunks) ----
#pragma unroll
        for (int kb = 0; kb < 64; kb += 16) {
            uint32_t a0, a1, a2, a3;
            ldsm_x4(a0, a1, a2, a3, poff + (kb << 1));
#pragma unroll
            for (int g = 0; g < 4; g++) {
                uint32_t b0, b1, b2, b3;
                ldsm_x4_trans(b0, b1, b2, b3, vstage + voff[g] + kb * 272);
                mma_f16(o[2 * g],     a0, a1, a2, a3, b0, b1);
                mma_f16(o[2 * g + 1], a0, a1, a2, a3, b2, b3);
            }
        }
    }

    // ---- epilogue: fp16 y ----
    const float inv0 = 1.0f / l0_;
    const float inv1 = 1.0f / l1_;
    const int r0g = q0 + mbase + gid;
    __half* y0p = g_y16 + ((size_t)(b * NT) + r0g) * 2048 + h * ND;
    __half* y1p = y0p + (size_t)8 * 2048;
#pragma unroll
    for (int j = 0; j < 8; j++) {
        int c = (wn << 6) + (j << 3) + (tig << 1);
        *(__half2*)&y0p[c] = __floats2half2_rn(o[j][0] * inv0, o[j][1] * inv0);
        *(__half2*)&y1p[c] = __floats2half2_rn(o[j][2] * inv1, o[j][3] * inv1);
    }
}

// ============================================================
// launch
// ============================================================
extern "C" void kernel_launch(void* const* d_in, const int* in_sizes, int n_in,
                              void* d_out, int out_size)
{
    const float* x      = (const float*)d_in[0];
    const float* w_qkv  = (const float*)d_in[1];
    const float* w_proj = (const float*)d_in[2];
    const float* qw     = (const float*)d_in[3];
    const float* kw     = (const float*)d_in[4];
    float* out = (float*)d_out;

    float* qkv_ptr = nullptr;
    __half* x16_ptr = nullptr;
    __half* wqkvT16_ptr = nullptr;
    __half* wprojT16_ptr = nullptr;
    __half* y16_ptr = nullptr;
    cudaGetSymbolAddress((void**)&qkv_ptr, g_qkv);
    cudaGetSymbolAddress((void**)&x16_ptr, g_x16);
    cudaGetSymbolAddress((void**)&wqkvT16_ptr, g_wqkvT16);
    cudaGetSymbolAddress((void**)&wprojT16_ptr, g_wprojT16);
    cudaGetSymbolAddress((void**)&y16_ptr, g_y16);

    cudaFuncSetAttribute(gemm_f16_kernel,
                         cudaFuncAttributeMaxDynamicSharedMemorySize, GB_SMEM_BYTES);
    cudaFuncSetAttribute(flash_mma_kernel,
                         cudaFuncAttributeMaxDynamicSharedMemorySize, FB_SMEM_BYTES);

    // 1. RoPE tables
    rope_tables_kernel<<<(NT * 64 + 255) / 256, 256>>>();

    // 2. operand conversions: x -> fp16; weights -> transposed fp16
    {
        int n4 = BT * NC / 4;
        cvt16_kernel<<<(n4 + 255) / 256, 256>>>((const float4*)x, (uint2*)x16_ptr, n4);
        dim3 blk(32, 8);
        transpose16_kernel<<<dim3(C3 / 32, NC / 32), blk>>>(w_qkv, wqkvT16_ptr, NC, C3);
        transpose16_kernel<<<dim3(NC / 32, NC / 32), blk>>>(w_proj, wprojT16_ptr, NC, NC);
    }

    // 3. qkv = x @ w_qkv (fp16 mma, single GEMM over N=6144)
    {
        dim3 grid(C3 / 256, BT / 128);
        gemm_f16_kernel<<<grid, 256, GB_SMEM_BYTES>>>(
            x16_ptr, wqkvT16_ptr, qkv_ptr, NC, C3, 0);
    }

    // 4. RMSNorm + RoPE -> fp16 q,k; v -> fp16
    rmsrope_kernel<<<BT, 256>>>(qw, kw);

    // 5. flash attention (all fp16 MMA)
    {
        dim3 grid(NT / 64, NB * NH);
        flash_mma_kernel<<<grid, 256, FB_SMEM_BYTES>>>();
    }

    // 6. out = y @ w_proj (fp16 mma)
    {
        dim3 grid(NC / 256, BT / 128);
        gemm_f16_kernel<<<grid, 256, GB_SMEM_BYTES>>>(
            y16_ptr, wprojT16_ptr, out, NC, NC, 0);
    }
}